// round 10
// baseline (speedup 1.0000x reference)
#include <cuda_runtime.h>
#include <cstdint>

#define Bb 2
#define Sq 2048
#define Dm 1024
#define Hh 16
#define Dk 64

// Scratch (allocation-free rule: __device__ globals)
__device__ __align__(16) float g_qh[(size_t)Bb*Hh*Sq*Dk];
__device__ __align__(16) float g_kh[(size_t)Bb*Hh*Sq*Dk];
__device__ __align__(16) float g_vh[(size_t)Bb*Hh*Sq*Dk];
__device__ __align__(16) float g_ao[(size_t)Bb*Sq*Dm];

// ---------------------------------------------------------------------------
__device__ __forceinline__ uint32_t f2tf(float x) {
    uint32_t u;
    asm("cvt.rna.tf32.f32 %0, %1;" : "=r"(u) : "f"(x));
    return u;
}
__device__ __forceinline__ float f2tff(float x) { return __uint_as_float(f2tf(x)); }

__device__ __forceinline__ void mma_tf32(float c[4],
    uint32_t a0, uint32_t a1, uint32_t a2, uint32_t a3,
    uint32_t b0, uint32_t b1)
{
    asm volatile(
        "mma.sync.aligned.m16n8k8.row.col.f32.tf32.tf32.f32 "
        "{%0,%1,%2,%3}, {%4,%5,%6,%7}, {%8,%9}, {%0,%1,%2,%3};"
        : "+f"(c[0]), "+f"(c[1]), "+f"(c[2]), "+f"(c[3])
        : "r"(a0), "r"(a1), "r"(a2), "r"(a3), "r"(b0), "r"(b1));
}

__device__ __forceinline__ uint4 tf4(float4 v) {
    uint4 u;
    u.x = f2tf(v.x); u.y = f2tf(v.y); u.z = f2tf(v.z); u.w = f2tf(v.w);
    return u;
}

__device__ __forceinline__ void ldsm_x4(uint32_t& r0, uint32_t& r1,
                                        uint32_t& r2, uint32_t& r3, uint32_t addr)
{
    asm volatile("ldmatrix.sync.aligned.m8n8.x4.shared.b16 {%0,%1,%2,%3}, [%4];"
        : "=r"(r0), "=r"(r1), "=r"(r2), "=r"(r3) : "r"(addr));
}

__device__ __forceinline__ uint32_t s2u(const void* p) {
    return (uint32_t)__cvta_generic_to_shared(p);
}

// Vt chunk swizzle (proven in R8)
__device__ __forceinline__ int vswz(int d, int tok) {
    int f = ((d >> 3) & 7) ^ (d & 7);
    return ((((tok >> 2) ^ f) & 15) << 2) | (tok & 3);
}

// ============================================================================
// K1: fused Q/K/V projection (tf32 MMA, reg double-buffer, ldmatrix frags).
// Epilogue rounds outputs to tf32 so consumers can stage raw. (R8 proven)
// ============================================================================
__global__ __launch_bounds__(256) void proj_tc(
    const float* __restrict__ xq, const float* __restrict__ xk, const float* __restrict__ xv,
    const float* __restrict__ wq, const float* __restrict__ wk, const float* __restrict__ wv,
    const float* __restrict__ bq, const float* __restrict__ bk, const float* __restrict__ bv)
{
    const int which = blockIdx.z;
    const float* __restrict__ A    = which == 0 ? xq : (which == 1 ? xk : xv);
    const float* __restrict__ W    = which == 0 ? wq : (which == 1 ? wk : wv);
    const float* __restrict__ bias = which == 0 ? bq : (which == 1 ? bk : bv);
    float* __restrict__ dst        = which == 0 ? g_qh : (which == 1 ? g_kh : g_vh);

    __shared__ uint32_t As[2][128][20];
    __shared__ uint32_t Bs[2][128][20];

    const int tid = threadIdx.x;
    const int lane = tid & 31, wid = tid >> 5;
    const int wm = wid & 1, wn = wid >> 1;
    const int bm = blockIdx.y * 128, bn = blockIdx.x * 128;
    const int lr = lane >> 2, lc = lane & 3;

    const int row0 = tid >> 2,          kq0 = (tid & 3) << 2;
    const int row1 = (tid + 256) >> 2,  kq1 = ((tid + 256) & 3) << 2;

    const int a_r = (lane & 7) + ((lane >> 3) & 1) * 8;
    const int a_c = ((lane >> 4) & 1) * 4;
    const int b_sel = lane >> 3;
    const int b_r = ((b_sel >> 1) & 1) * 8 + (lane & 7);
    const int b_c = (b_sel & 1) * 4;

    const uint32_t sA = s2u(&As[0][0][0]);
    const uint32_t sB = s2u(&Bs[0][0][0]);

    float4 ra0, ra1, rb0, rb1;

#define PJ_LD(k0) do { \
    ra0 = *(const float4*)(A + (size_t)(bm + row0) * Dm + (k0) + kq0); \
    rb0 = *(const float4*)(W + (size_t)(bn + row0) * Dm + (k0) + kq0); \
    ra1 = *(const float4*)(A + (size_t)(bm + row1) * Dm + (k0) + kq1); \
    rb1 = *(const float4*)(W + (size_t)(bn + row1) * Dm + (k0) + kq1); \
} while (0)

#define PJ_ST(st) do { \
    *(uint4*)&As[st][row0][kq0] = tf4(ra0); \
    *(uint4*)&Bs[st][row0][kq0] = tf4(rb0); \
    *(uint4*)&As[st][row1][kq1] = tf4(ra1); \
    *(uint4*)&Bs[st][row1][kq1] = tf4(rb1); \
} while (0)

    float acc[4][4][4];
#pragma unroll
    for (int i = 0; i < 4; i++)
#pragma unroll
        for (int j = 0; j < 4; j++)
#pragma unroll
            for (int t = 0; t < 4; t++) acc[i][j][t] = 0.f;

    PJ_LD(0); PJ_ST(0); __syncthreads();

    for (int it = 0; it < 64; it++) {
        const int cur = it & 1;
        if (it < 63) PJ_LD((it + 1) * 16);
#pragma unroll
        for (int ks = 0; ks < 16; ks += 8) {
            uint32_t af[4][4], bf[4][2];
#pragma unroll
            for (int mt = 0; mt < 4; mt++)
                ldsm_x4(af[mt][0], af[mt][1], af[mt][2], af[mt][3],
                    sA + ((cur * 128 + wm * 64 + mt * 16 + a_r) * 20 + ks + a_c) * 4);
#pragma unroll
            for (int ntp = 0; ntp < 2; ntp++)
                ldsm_x4(bf[2 * ntp][0], bf[2 * ntp][1], bf[2 * ntp + 1][0], bf[2 * ntp + 1][1],
                    sB + ((cur * 128 + wn * 32 + ntp * 16 + b_r) * 20 + ks + b_c) * 4);
#pragma unroll
            for (int mt = 0; mt < 4; mt++)
#pragma unroll
                for (int nt = 0; nt < 4; nt++)
                    mma_tf32(acc[mt][nt], af[mt][0], af[mt][1], af[mt][2], af[mt][3],
                             bf[nt][0], bf[nt][1]);
        }
        if (it < 63) PJ_ST(cur ^ 1);
        __syncthreads();
    }

#pragma unroll
    for (int mt = 0; mt < 4; mt++) {
#pragma unroll
        for (int nt = 0; nt < 4; nt++) {
            int col = bn + wn * 32 + nt * 8 + lc * 2;
            int h = col >> 6, d = col & 63;
            float b0 = bias[col], b1 = bias[col + 1];
#pragma unroll
            for (int half = 0; half < 2; half++) {
                int m = bm + wm * 64 + mt * 16 + lr + half * 8;
                int b = m >> 11;
                int s = m & (Sq - 1);
                float2 v;
                v.x = f2tff(acc[mt][nt][half * 2 + 0] + b0);
                v.y = f2tff(acc[mt][nt][half * 2 + 1] + b1);
                *(float2*)(dst + (((size_t)(b * Hh + h) * Sq + s) << 6) + d) = v;
            }
        }
    }
#undef PJ_LD
#undef PJ_ST
}

// ============================================================================
// K2: fused attention, TWO-PASS, no max-subtraction, writes NORMALIZED
// scores directly (no separate norm kernel).
//  Pass A: stream K, QK -> exp -> row sums.
//  Pass B: recompute QK, p = e*inv, stage+write p, O += P@V (normalized).
// ============================================================================
#define QT 256

__global__ __launch_bounds__(512, 1) void attn_fused(
    const int* __restrict__ mask, float* __restrict__ sc)
{
    extern __shared__ float sh[];
    float (*Qs)[68]     = (float(*)[68])sh;                            // [q256][d]
    float (*Ks)[64][68] = (float(*)[64][68])(sh + 17408);              // [st][tok][d]
    float (*Vt)[64][64] = (float(*)[64][64])(sh + 17408 + 8704);       // [st][d][tok] swizzled
    float (*Ps)[68]     = (float(*)[68])(sh + 17408 + 8704 + 8192);    // [q][k]

    const int bh = blockIdx.y;
    const int b = bh >> 4, h = bh & 15;
    const int q0 = blockIdx.x * QT;
    const float* qp    = g_qh + ((size_t)bh * Sq + q0) * Dk;
    const float* kbase = g_kh + (size_t)bh * Sq * Dk;
    const float* vbase = g_vh + (size_t)bh * Sq * Dk;

    const int tid = threadIdx.x;
    const int lane = tid & 31, w = tid >> 5;          // 16 warps
    const int lr = lane >> 2, lc = lane & 3;
    const int r0 = 16 * w + lr;                        // local q row; second = r0+8
    const int qg0 = q0 + r0;

    const int a_r = (lane & 7) + ((lane >> 3) & 1) * 8;
    const int a_c = ((lane >> 4) & 1) * 4;
    const int b_sel = lane >> 3;
    const int b_r = ((b_sel >> 1) & 1) * 8 + (lane & 7);
    const int b_c = (b_sel & 1) * 4;

    const uint32_t sK = s2u(&Ks[0][0][0]);
    const uint32_t sV = s2u(&Vt[0][0][0]);
    const uint32_t qaddr = s2u(&Qs[16 * w + a_r][a_c]);
    const uint32_t paddr = s2u(&Ps[16 * w + a_r][a_c]);

    const int rA = tid >> 4, cA = (tid & 15) << 2;    // K/V tile: 64x64, 2 f4/thread
    const int rB = rA + 32;

    float4 rk0, rk1, rv0, rv1;

#define AT_LDK(kt) do { \
    rk0 = *(const float4*)(kbase + (size_t)((kt) + rA) * Dk + cA); \
    rk1 = *(const float4*)(kbase + (size_t)((kt) + rB) * Dk + cA); \
} while (0)
#define AT_STK(st) do { \
    *(float4*)&Ks[st][rA][cA] = rk0; \
    *(float4*)&Ks[st][rB][cA] = rk1; \
} while (0)
#define AT_LDV(kt) do { \
    rv0 = *(const float4*)(vbase + (size_t)((kt) + rA) * Dk + cA); \
    rv1 = *(const float4*)(vbase + (size_t)((kt) + rB) * Dk + cA); \
} while (0)
#define AT_STV(st) do { \
    Vt[st][cA + 0][vswz(cA + 0, rA)] = rv0.x; \
    Vt[st][cA + 1][vswz(cA + 1, rA)] = rv0.y; \
    Vt[st][cA + 2][vswz(cA + 2, rA)] = rv0.z; \
    Vt[st][cA + 3][vswz(cA + 3, rA)] = rv0.w; \
    Vt[st][cA + 0][vswz(cA + 0, rB)] = rv1.x; \
    Vt[st][cA + 1][vswz(cA + 1, rB)] = rv1.y; \
    Vt[st][cA + 2][vswz(cA + 2, rB)] = rv1.z; \
    Vt[st][cA + 3][vswz(cA + 3, rB)] = rv1.w; \
} while (0)

    // load Q tile -> Qs[q][d]  (already tf32-rounded by proj)
#pragma unroll
    for (int t = 0; t < 2; t++) {
        int f = tid + t * 512;
        int row = f >> 2;
        int c4 = (f & 3) << 4;
#pragma unroll
        for (int u = 0; u < 4; u++)
            *(float4*)&Qs[row][c4 + u * 4] =
                *(const float4*)(qp + row * Dk + c4 + u * 4);
    }

    const int* mrow0 = mask + ((size_t)b * Sq + qg0) * Sq;
    const int* mrow1 = mrow0 + 8 * Sq;

    float lsum0 = 0.f, lsum1 = 0.f;

    // ---------------- PASS A: row sums only (K only, no V, no writes) -------
    AT_LDK(0); AT_STK(0); __syncthreads();

    for (int it = 0; it < Sq / 64; it++) {
        const int cur = it & 1;
        const int kt = it * 64;
        if (it < Sq / 64 - 1) AT_LDK(kt + 64);

        float acc[8][4];
#pragma unroll
        for (int nt = 0; nt < 8; nt++)
#pragma unroll
            for (int e = 0; e < 4; e++) acc[nt][e] = 0.f;

#pragma unroll
        for (int ks = 0; ks < 64; ks += 8) {
            uint32_t qa[4], kb[8][2];
            ldsm_x4(qa[0], qa[1], qa[2], qa[3], qaddr + ks * 4);
#pragma unroll
            for (int ntp = 0; ntp < 4; ntp++)
                ldsm_x4(kb[2 * ntp][0], kb[2 * ntp][1], kb[2 * ntp + 1][0], kb[2 * ntp + 1][1],
                    sK + ((cur * 64 + ntp * 16 + b_r) * 68 + ks + b_c) * 4);
#pragma unroll
            for (int nt = 0; nt < 8; nt++)
                mma_tf32(acc[nt], qa[0], qa[1], qa[2], qa[3], kb[nt][0], kb[nt][1]);
        }

#pragma unroll
        for (int nt = 0; nt < 8; nt++) {
            int kc = kt + nt * 8 + lc * 2;
            int2 ma = *(const int2*)(mrow0 + kc);
            int2 mb = *(const int2*)(mrow1 + kc);
            lsum0 += ((ma.x == 0) ? 0.f : __expf(acc[nt][0] * 0.125f))
                   + ((ma.y == 0) ? 0.f : __expf(acc[nt][1] * 0.125f));
            lsum1 += ((mb.x == 0) ? 0.f : __expf(acc[nt][2] * 0.125f))
                   + ((mb.y == 0) ? 0.f : __expf(acc[nt][3] * 0.125f));
        }

        if (it < Sq / 64 - 1) AT_STK(cur ^ 1);
        __syncthreads();
    }

    // reduce row sums over the 4 lc lanes
    lsum0 += __shfl_xor_sync(0xffffffffu, lsum0, 1);
    lsum0 += __shfl_xor_sync(0xffffffffu, lsum0, 2);
    lsum1 += __shfl_xor_sync(0xffffffffu, lsum1, 1);
    lsum1 += __shfl_xor_sync(0xffffffffu, lsum1, 2);
    const float inv0 = 1.0f / lsum0, inv1 = 1.0f / lsum1;

    float o_acc[8][4];
#pragma unroll
    for (int nt = 0; nt < 8; nt++)
#pragma unroll
        for (int e = 0; e < 4; e++) o_acc[nt][e] = 0.f;

    // ---------------- PASS B: normalized write + EV --------------------------
    AT_LDK(0); AT_LDV(0); AT_STK(0); AT_STV(0); __syncthreads();

    for (int it = 0; it < Sq / 64; it++) {
        const int cur = it & 1;
        const int kt = it * 64;
        if (it < Sq / 64 - 1) { AT_LDK(kt + 64); AT_LDV(kt + 64); }

        float acc[8][4];
#pragma unroll
        for (int nt = 0; nt < 8; nt++)
#pragma unroll
            for (int e = 0; e < 4; e++) acc[nt][e] = 0.f;

#pragma unroll
        for (int ks = 0; ks < 64; ks += 8) {
            uint32_t qa[4], kb[8][2];
            ldsm_x4(qa[0], qa[1], qa[2], qa[3], qaddr + ks * 4);
#pragma unroll
            for (int ntp = 0; ntp < 4; ntp++)
                ldsm_x4(kb[2 * ntp][0], kb[2 * ntp][1], kb[2 * ntp + 1][0], kb[2 * ntp + 1][1],
                    sK + ((cur * 64 + ntp * 16 + b_r) * 68 + ks + b_c) * 4);
#pragma unroll
            for (int nt = 0; nt < 8; nt++)
                mma_tf32(acc[nt], qa[0], qa[1], qa[2], qa[3], kb[nt][0], kb[nt][1]);
        }

        // normalized p, stage into Ps
#pragma unroll
        for (int nt = 0; nt < 8; nt++) {
            int kc = kt + nt * 8 + lc * 2;
            int2 ma = *(const int2*)(mrow0 + kc);
            int2 mb = *(const int2*)(mrow1 + kc);
            float p00 = (ma.x == 0) ? 0.f : __expf(acc[nt][0] * 0.125f) * inv0;
            float p01 = (ma.y == 0) ? 0.f : __expf(acc[nt][1] * 0.125f) * inv0;
            float p10 = (mb.x == 0) ? 0.f : __expf(acc[nt][2] * 0.125f) * inv1;
            float p11 = (mb.y == 0) ? 0.f : __expf(acc[nt][3] * 0.125f) * inv1;
            int cl = nt * 8 + lc * 2;
            Ps[r0][cl]         = p00;
            Ps[r0][cl + 1]     = p01;
            Ps[r0 + 8][cl]     = p10;
            Ps[r0 + 8][cl + 1] = p11;
        }
        __syncthreads();

        // coalesced write of FINAL normalized p tile (256 rows x 64 cols)
#pragma unroll
        for (int t = 0; t < 8; t++) {
            int f = tid + t * 512;
            int row = f >> 4;
            int c4 = (f & 15) << 2;
            float4 v = *(const float4*)&Ps[row][c4];
            *(float4*)(sc + (((size_t)(b * Sq + q0 + row)) * Hh + h) * Sq + kt + c4) = v;
        }

        // O += P @ V via ldmatrix on swizzled Vt (P already normalized)
#pragma unroll
        for (int ks = 0; ks < 64; ks += 8) {
            uint32_t pa[4], vb[8][2];
            ldsm_x4(pa[0], pa[1], pa[2], pa[3], paddr + ks * 4);
#pragma unroll
            for (int ntp = 0; ntp < 4; ntp++) {
                int d = ntp * 16 + b_r;
                int f = ((d >> 3) & 7) ^ (d & 7);
                int chunk = (((ks + b_c) >> 2) ^ f) & 15;
                ldsm_x4(vb[2 * ntp][0], vb[2 * ntp][1], vb[2 * ntp + 1][0], vb[2 * ntp + 1][1],
                    sV + ((cur * 64 + d) * 64 + (chunk << 2)) * 4);
            }
#pragma unroll
            for (int nt = 0; nt < 8; nt++)
                mma_tf32(o_acc[nt], pa[0], pa[1], pa[2], pa[3], vb[nt][0], vb[nt][1]);
        }

        if (it < Sq / 64 - 1) { AT_STK(cur ^ 1); AT_STV(cur ^ 1); }
        __syncthreads();
    }

    // epilogue: write O (pre-rounded to tf32 for outproj) to g_ao
    float* orow0 = g_ao + (size_t)(b * Sq + qg0) * Dm + h * Dk;
    float* orow1 = orow0 + 8 * Dm;
#pragma unroll
    for (int nt = 0; nt < 8; nt++) {
        int d = nt * 8 + lc * 2;
        *(float2*)(orow0 + d) = make_float2(f2tff(o_acc[nt][0]), f2tff(o_acc[nt][1]));
        *(float2*)(orow1 + d) = make_float2(f2tff(o_acc[nt][2]), f2tff(o_acc[nt][3]));
    }
#undef AT_LDK
#undef AT_STK
#undef AT_LDV
#undef AT_STV
}

// ============================================================================
// K4: final projection out = g_ao @ Wo^T + bo. (R8 proven)
// ============================================================================
__global__ __launch_bounds__(256) void outproj_tc(
    const float* __restrict__ W, const float* __restrict__ bias, float* __restrict__ C)
{
    __shared__ float    As[2][128][20];
    __shared__ uint32_t Bs[2][128][20];
    const int tid = threadIdx.x;
    const int lane = tid & 31, wid = tid >> 5;
    const int wm = wid & 1, wn = wid >> 1;
    const int bm = blockIdx.y * 128, bn = blockIdx.x * 128;
    const int lr = lane >> 2, lc = lane & 3;
    const float* __restrict__ A = g_ao;

    const int row0 = tid >> 2,          kq0 = (tid & 3) << 2;
    const int row1 = (tid + 256) >> 2,  kq1 = ((tid + 256) & 3) << 2;

    const int a_r = (lane & 7) + ((lane >> 3) & 1) * 8;
    const int a_c = ((lane >> 4) & 1) * 4;
    const int b_sel = lane >> 3;
    const int b_r = ((b_sel >> 1) & 1) * 8 + (lane & 7);
    const int b_c = (b_sel & 1) * 4;

    const uint32_t sA = s2u(&As[0][0][0]);
    const uint32_t sB = s2u(&Bs[0][0][0]);

    float4 ra0, ra1, rb0, rb1;

#define OP_LD(k0) do { \
    ra0 = *(const float4*)(A + (size_t)(bm + row0) * Dm + (k0) + kq0); \
    rb0 = *(const float4*)(W + (size_t)(bn + row0) * Dm + (k0) + kq0); \
    ra1 = *(const float4*)(A + (size_t)(bm + row1) * Dm + (k0) + kq1); \
    rb1 = *(const float4*)(W + (size_t)(bn + row1) * Dm + (k0) + kq1); \
} while (0)

#define OP_ST(st) do { \
    *(float4*)&As[st][row0][kq0] = ra0; \
    *(uint4*)&Bs[st][row0][kq0] = tf4(rb0); \
    *(float4*)&As[st][row1][kq1] = ra1; \
    *(uint4*)&Bs[st][row1][kq1] = tf4(rb1); \
} while (0)

    float acc[4][4][4];
#pragma unroll
    for (int i = 0; i < 4; i++)
#pragma unroll
        for (int j = 0; j < 4; j++)
#pragma unroll
            for (int t = 0; t < 4; t++) acc[i][j][t] = 0.f;

    OP_LD(0); OP_ST(0); __syncthreads();

    for (int it = 0; it < 64; it++) {
        const int cur = it & 1;
        if (it < 63) OP_LD((it + 1) * 16);
#pragma unroll
        for (int ks = 0; ks < 16; ks += 8) {
            uint32_t af[4][4], bf[4][2];
#pragma unroll
            for (int mt = 0; mt < 4; mt++)
                ldsm_x4(af[mt][0], af[mt][1], af[mt][2], af[mt][3],
                    sA + ((cur * 128 + wm * 64 + mt * 16 + a_r) * 20 + ks + a_c) * 4);
#pragma unroll
            for (int ntp = 0; ntp < 2; ntp++)
                ldsm_x4(bf[2 * ntp][0], bf[2 * ntp][1], bf[2 * ntp + 1][0], bf[2 * ntp + 1][1],
                    sB + ((cur * 128 + wn * 32 + ntp * 16 + b_r) * 20 + ks + b_c) * 4);
#pragma unroll
            for (int mt = 0; mt < 4; mt++)
#pragma unroll
                for (int nt = 0; nt < 4; nt++)
                    mma_tf32(acc[mt][nt], af[mt][0], af[mt][1], af[mt][2], af[mt][3],
                             bf[nt][0], bf[nt][1]);
        }
        if (it < 63) OP_ST(cur ^ 1);
        __syncthreads();
    }

#pragma unroll
    for (int mt = 0; mt < 4; mt++) {
#pragma unroll
        for (int nt = 0; nt < 4; nt++) {
            int col = bn + wn * 32 + nt * 8 + lc * 2;
            float b0 = bias[col], b1 = bias[col + 1];
#pragma unroll
            for (int half = 0; half < 2; half++) {
                int m = bm + wm * 64 + mt * 16 + lr + half * 8;
                float2 v;
                v.x = acc[mt][nt][half * 2 + 0] + b0;
                v.y = acc[mt][nt][half * 2 + 1] + b1;
                *(float2*)(C + (size_t)m * Dm + col) = v;
            }
        }
    }
#undef OP_LD
#undef OP_ST
}

// ============================================================================
extern "C" void kernel_launch(void* const* d_in, const int* in_sizes, int n_in,
                              void* d_out, int out_size)
{
    const float* q    = (const float*)d_in[0];
    const float* k    = (const float*)d_in[1];
    const float* v    = (const float*)d_in[2];
    const int*   mask = (const int*)d_in[3];
    const float* Wq   = (const float*)d_in[4];
    const float* bq   = (const float*)d_in[5];
    const float* Wk   = (const float*)d_in[6];
    const float* bk   = (const float*)d_in[7];
    const float* Wv   = (const float*)d_in[8];
    const float* bv   = (const float*)d_in[9];
    const float* Wo   = (const float*)d_in[10];
    const float* bo   = (const float*)d_in[11];

    float* out = (float*)d_out;
    float* sc  = out + (size_t)Bb * Sq * Dm;   // scores_out region

    const int attn_smem = (256 * 68 + 2 * 64 * 68 + 2 * 64 * 64 + 256 * 68) * 4; // 206848
    cudaFuncSetAttribute(attn_fused, cudaFuncAttributeMaxDynamicSharedMemorySize, attn_smem);

    dim3 gp(Dm / 128, (Bb * Sq) / 128, 3);
    proj_tc<<<gp, 256>>>(q, k, v, Wq, Wk, Wv, bq, bk, bv);

    dim3 ga(Sq / QT, Bb * Hh);
    attn_fused<<<ga, 512, attn_smem>>>(mask, sc);

    dim3 go(Dm / 128, (Bb * Sq) / 128);
    outproj_tc<<<go, 256>>>(Wo, bo, out);
}

// round 11
// speedup vs baseline: 1.2908x; 1.2908x over previous
#include <cuda_runtime.h>
#include <cuda_fp16.h>
#include <cstdint>

#define Bb 2
#define Sq 2048
#define Dm 1024
#define Hh 16
#define Dk 64

// Scratch (allocation-free rule: __device__ globals) — f16 intermediates
__device__ __align__(16) __half g_qh[(size_t)Bb*Hh*Sq*Dk];
__device__ __align__(16) __half g_kh[(size_t)Bb*Hh*Sq*Dk];
__device__ __align__(16) __half g_vh[(size_t)Bb*Hh*Sq*Dk];
__device__ __align__(16) __half g_ao[(size_t)Bb*Sq*Dm];
__device__ __align__(16) float  g_linv[(size_t)Bb*Sq*Hh];

// ---------------------------------------------------------------------------
__device__ __forceinline__ uint32_t h2u(float a, float b) {
    __half2 h = __floats2half2_rn(a, b);
    return *(uint32_t*)&h;
}

__device__ __forceinline__ uint4 f8h(float4 a, float4 b) {
    uint4 r;
    r.x = h2u(a.x, a.y); r.y = h2u(a.z, a.w);
    r.z = h2u(b.x, b.y); r.w = h2u(b.z, b.w);
    return r;
}

__device__ __forceinline__ void mma_f16(float c[4],
    uint32_t a0, uint32_t a1, uint32_t a2, uint32_t a3,
    uint32_t b0, uint32_t b1)
{
    asm volatile(
        "mma.sync.aligned.m16n8k16.row.col.f32.f16.f16.f32 "
        "{%0,%1,%2,%3}, {%4,%5,%6,%7}, {%8,%9}, {%0,%1,%2,%3};"
        : "+f"(c[0]), "+f"(c[1]), "+f"(c[2]), "+f"(c[3])
        : "r"(a0), "r"(a1), "r"(a2), "r"(a3), "r"(b0), "r"(b1));
}

__device__ __forceinline__ void ldsm_x4(uint32_t& r0, uint32_t& r1,
                                        uint32_t& r2, uint32_t& r3, uint32_t addr)
{
    asm volatile("ldmatrix.sync.aligned.m8n8.x4.shared.b16 {%0,%1,%2,%3}, [%4];"
        : "=r"(r0), "=r"(r1), "=r"(r2), "=r"(r3) : "r"(addr));
}

__device__ __forceinline__ void ldsm_x4_t(uint32_t& r0, uint32_t& r1,
                                          uint32_t& r2, uint32_t& r3, uint32_t addr)
{
    asm volatile("ldmatrix.sync.aligned.m8n8.x4.trans.shared.b16 {%0,%1,%2,%3}, [%4];"
        : "=r"(r0), "=r"(r1), "=r"(r2), "=r"(r3) : "r"(addr));
}

__device__ __forceinline__ uint32_t s2u(const void* p) {
    return (uint32_t)__cvta_generic_to_shared(p);
}

// ============================================================================
// K1: fused Q/K/V projection, fp16 m16n8k16. 128x128 block, BK=16.
// 8 warps 2(m) x 4(n), warp tile 64x32.  Outputs f16 head-layout tensors.
// ============================================================================
__global__ __launch_bounds__(256) void proj_tc(
    const float* __restrict__ xq, const float* __restrict__ xk, const float* __restrict__ xv,
    const float* __restrict__ wq, const float* __restrict__ wk, const float* __restrict__ wv,
    const float* __restrict__ bq, const float* __restrict__ bk, const float* __restrict__ bv)
{
    const int which = blockIdx.z;
    const float* __restrict__ A    = which == 0 ? xq : (which == 1 ? xk : xv);
    const float* __restrict__ W    = which == 0 ? wq : (which == 1 ? wk : wv);
    const float* __restrict__ bias = which == 0 ? bq : (which == 1 ? bk : bv);
    __half* __restrict__ dst       = which == 0 ? g_qh : (which == 1 ? g_kh : g_vh);

    __shared__ __half As[2][128][24];   // [st][row m][k16], stride 48B
    __shared__ __half Bs[2][128][24];   // [st][row n][k16]

    const int tid = threadIdx.x;
    const int lane = tid & 31, wid = tid >> 5;
    const int wm = wid & 1, wn = wid >> 1;
    const int bm = blockIdx.y * 128, bn = blockIdx.x * 128;
    const int lr = lane >> 2, lc = lane & 3;

    // staging: thread -> (row, 16B seg): 128 rows x 2 segs (8 k each)
    const int row0 = tid >> 1, seg = (tid & 1) * 8;

    // ldmatrix lane mapping (b16 canonical)
    const int a_row = lane & 15;                 // A rows within 16
    const int a_cB  = ((lane >> 4) & 1) * 16;    // byte col 0/16
    const int b_row = (lane & 7) + ((lane >> 3) & 1) * 8;
    const int b_cB  = ((lane >> 4) & 1) * 16;

    const uint32_t sA = s2u(&As[0][0][0]);
    const uint32_t sB = s2u(&Bs[0][0][0]);

    float4 ra0, ra1, rb0, rb1;

#define PJ_LD(k0) do { \
    ra0 = *(const float4*)(A + (size_t)(bm + row0) * Dm + (k0) + seg); \
    ra1 = *(const float4*)(A + (size_t)(bm + row0) * Dm + (k0) + seg + 4); \
    rb0 = *(const float4*)(W + (size_t)(bn + row0) * Dm + (k0) + seg); \
    rb1 = *(const float4*)(W + (size_t)(bn + row0) * Dm + (k0) + seg + 4); \
} while (0)

#define PJ_ST(st) do { \
    *(uint4*)&As[st][row0][seg] = f8h(ra0, ra1); \
    *(uint4*)&Bs[st][row0][seg] = f8h(rb0, rb1); \
} while (0)

    float acc[4][4][4];
#pragma unroll
    for (int i = 0; i < 4; i++)
#pragma unroll
        for (int j = 0; j < 4; j++)
#pragma unroll
            for (int t = 0; t < 4; t++) acc[i][j][t] = 0.f;

    PJ_LD(0); PJ_ST(0); __syncthreads();

    for (int it = 0; it < 64; it++) {
        const int cur = it & 1;
        if (it < 63) PJ_LD((it + 1) * 16);

        uint32_t af[4][4], bf[4][2];
#pragma unroll
        for (int mt = 0; mt < 4; mt++)
            ldsm_x4(af[mt][0], af[mt][1], af[mt][2], af[mt][3],
                sA + (cur * 128 + wm * 64 + mt * 16 + a_row) * 48 + a_cB);
#pragma unroll
        for (int ntp = 0; ntp < 2; ntp++) {
            uint32_t r0, r1, r2, r3;
            ldsm_x4(r0, r1, r2, r3,
                sB + (cur * 128 + wn * 32 + ntp * 16 + b_row) * 48 + b_cB);
            bf[2 * ntp][0] = r0; bf[2 * ntp][1] = r2;       // non-trans mapping
            bf[2 * ntp + 1][0] = r1; bf[2 * ntp + 1][1] = r3;
        }
#pragma unroll
        for (int mt = 0; mt < 4; mt++)
#pragma unroll
            for (int nt = 0; nt < 4; nt++)
                mma_f16(acc[mt][nt], af[mt][0], af[mt][1], af[mt][2], af[mt][3],
                        bf[nt][0], bf[nt][1]);

        if (it < 63) PJ_ST(cur ^ 1);
        __syncthreads();
    }

#pragma unroll
    for (int mt = 0; mt < 4; mt++) {
#pragma unroll
        for (int nt = 0; nt < 4; nt++) {
            int col = bn + wn * 32 + nt * 8 + lc * 2;
            int h = col >> 6, d = col & 63;
            float b0 = bias[col], b1 = bias[col + 1];
#pragma unroll
            for (int half = 0; half < 2; half++) {
                int m = bm + wm * 64 + mt * 16 + lr + half * 8;
                int b = m >> 11;
                int s = m & (Sq - 1);
                __half2 hv = __floats2half2_rn(acc[mt][nt][half * 2 + 0] + b0,
                                               acc[mt][nt][half * 2 + 1] + b1);
                *(__half2*)(dst + (((size_t)(b * Hh + h) * Sq + s) << 6) + d) = hv;
            }
        }
    }
#undef PJ_LD
#undef PJ_ST
}

// ============================================================================
// K2: fused attention, single pass, no max-subtraction (fp16 mma).
// QK accumulator fragments feed EV A-operand DIRECTLY from registers.
// Writes UNNORMALIZED exp(s) (fp32) + 1/rowsum; norm kernel rescales.
// 512 threads, q-tile 256, double-buffered K/V (f16), V read via ldsm.trans.
// ============================================================================
#define QT 256

__global__ __launch_bounds__(512, 1) void attn_fused(
    const int* __restrict__ mask, float* __restrict__ sc)
{
    extern __shared__ char shb[];
    __half (*Qs)[72]     = (__half(*)[72])shb;                  // [q256][d], 144B rows
    __half (*Ks)[64][72] = (__half(*)[64][72])(shb + 36864);    // [st][tok][d]
    __half (*Vs)[64][72] = (__half(*)[64][72])(shb + 55296);    // [st][tok][d]
    float  (*Ps)[68]     = (float(*)[68])(shb + 73728);         // [q][k] fp32 (write staging)

    const int bh = blockIdx.y;
    const int b = bh >> 4, h = bh & 15;
    const int q0 = blockIdx.x * QT;
    const __half* qp    = g_qh + ((size_t)bh * Sq + q0) * Dk;
    const __half* kbase = g_kh + (size_t)bh * Sq * Dk;
    const __half* vbase = g_vh + (size_t)bh * Sq * Dk;

    const int tid = threadIdx.x;
    const int lane = tid & 31, w = tid >> 5;          // 16 warps
    const int lr = lane >> 2, lc = lane & 3;
    const int r0 = 16 * w + lr;                        // local q row; second = r0+8
    const int qg0 = q0 + r0;

    const int a_row = lane & 15;
    const int a_cB  = ((lane >> 4) & 1) * 16;
    const int b_row = (lane & 7) + ((lane >> 3) & 1) * 8;
    const int b_cB  = ((lane >> 4) & 1) * 16;

    const uint32_t sQ = s2u(&Qs[0][0]);
    const uint32_t sK = s2u(&Ks[0][0][0]);
    const uint32_t sV = s2u(&Vs[0][0][0]);

    // K/V staging: 64 rows x 8 segs (16B = 8 halfs); 512 threads, 1 uint4 each
    const int rA = tid >> 3, segA = (tid & 7) * 8;

    uint4 rk, rv;

#define AT_LDK(kt) rk = *(const uint4*)(kbase + (size_t)((kt) + rA) * Dk + segA)
#define AT_STK(st) *(uint4*)&Ks[st][rA][segA] = rk
#define AT_LDV(kt) rv = *(const uint4*)(vbase + (size_t)((kt) + rA) * Dk + segA)
#define AT_STV(st) *(uint4*)&Vs[st][rA][segA] = rv

    // load Q tile (f16): 256 rows x 8 segs = 2048 uint4; 512 thr x 4
#pragma unroll
    for (int t = 0; t < 4; t++) {
        int f = tid + t * 512;
        int row = f >> 3;
        int sg = (f & 7) * 8;
        *(uint4*)&Qs[row][sg] = *(const uint4*)(qp + row * Dk + sg);
    }

    const int* mrow0 = mask + ((size_t)b * Sq + qg0) * Sq;
    const int* mrow1 = mrow0 + 8 * Sq;

    float lsum0 = 0.f, lsum1 = 0.f;
    float o_acc[8][4];
#pragma unroll
    for (int nt = 0; nt < 8; nt++)
#pragma unroll
        for (int e = 0; e < 4; e++) o_acc[nt][e] = 0.f;

    AT_LDK(0); AT_LDV(0); AT_STK(0); AT_STV(0); __syncthreads();

    for (int it = 0; it < Sq / 64; it++) {
        const int cur = it & 1;
        const int kt = it * 64;
        if (it < Sq / 64 - 1) { AT_LDK(kt + 64); AT_LDV(kt + 64); }

        float acc[8][4];
#pragma unroll
        for (int nt = 0; nt < 8; nt++)
#pragma unroll
            for (int e = 0; e < 4; e++) acc[nt][e] = 0.f;

        // ---- QK^T: 4 k16-groups over d ----
#pragma unroll
        for (int g = 0; g < 4; g++) {
            uint32_t qa[4], kb[8][2];
            ldsm_x4(qa[0], qa[1], qa[2], qa[3],
                sQ + (16 * w + a_row) * 144 + g * 32 + a_cB);
#pragma unroll
            for (int ntp = 0; ntp < 4; ntp++) {
                uint32_t r0u, r1u, r2u, r3u;
                ldsm_x4(r0u, r1u, r2u, r3u,
                    sK + (cur * 64 + ntp * 16 + b_row) * 144 + g * 32 + b_cB);
                kb[2 * ntp][0] = r0u; kb[2 * ntp][1] = r2u;
                kb[2 * ntp + 1][0] = r1u; kb[2 * ntp + 1][1] = r3u;
            }
#pragma unroll
            for (int nt = 0; nt < 8; nt++)
                mma_f16(acc[nt], qa[0], qa[1], qa[2], qa[3], kb[nt][0], kb[nt][1]);
        }

        // ---- exp (no max), mask -> 0, row sums; keep e in regs + stage fp32 ----
#pragma unroll
        for (int nt = 0; nt < 8; nt++) {
            int kc = kt + nt * 8 + lc * 2;
            int2 ma = *(const int2*)(mrow0 + kc);
            int2 mb = *(const int2*)(mrow1 + kc);
            float e00 = (ma.x == 0) ? 0.f : __expf(acc[nt][0] * 0.125f);
            float e01 = (ma.y == 0) ? 0.f : __expf(acc[nt][1] * 0.125f);
            float e10 = (mb.x == 0) ? 0.f : __expf(acc[nt][2] * 0.125f);
            float e11 = (mb.y == 0) ? 0.f : __expf(acc[nt][3] * 0.125f);
            lsum0 += e00 + e01;
            lsum1 += e10 + e11;
            acc[nt][0] = e00; acc[nt][1] = e01;
            acc[nt][2] = e10; acc[nt][3] = e11;
            int cl = nt * 8 + lc * 2;
            Ps[r0][cl]         = e00;
            Ps[r0][cl + 1]     = e01;
            Ps[r0 + 8][cl]     = e10;
            Ps[r0 + 8][cl + 1] = e11;
        }
        __syncthreads();

        // coalesced write of unnormalized E tile (256 rows x 64 cols, fp32)
#pragma unroll
        for (int t = 0; t < 8; t++) {
            int f = tid + t * 512;
            int row = f >> 4;
            int c4 = (f & 15) << 2;
            float4 v = *(const float4*)&Ps[row][c4];
            *(float4*)(sc + (((size_t)(b * Sq + q0 + row)) * Hh + h) * Sq + kt + c4) = v;
        }

        // ---- O += E @ V: A from registers (QK frag == A frag), B via ldsm.trans
#pragma unroll
        for (int g = 0; g < 4; g++) {
            uint32_t a0 = h2u(acc[2 * g][0],     acc[2 * g][1]);
            uint32_t a1 = h2u(acc[2 * g][2],     acc[2 * g][3]);
            uint32_t a2 = h2u(acc[2 * g + 1][0], acc[2 * g + 1][1]);
            uint32_t a3 = h2u(acc[2 * g + 1][2], acc[2 * g + 1][3]);
            uint32_t vb[8][2];
#pragma unroll
            for (int ntp = 0; ntp < 4; ntp++) {
                uint32_t r0u, r1u, r2u, r3u;
                ldsm_x4_t(r0u, r1u, r2u, r3u,
                    sV + (cur * 64 + g * 16 + b_row) * 144 + ntp * 32 + b_cB);
                vb[2 * ntp][0] = r0u; vb[2 * ntp][1] = r1u;   // trans mapping
                vb[2 * ntp + 1][0] = r2u; vb[2 * ntp + 1][1] = r3u;
            }
#pragma unroll
            for (int nt = 0; nt < 8; nt++)
                mma_f16(o_acc[nt], a0, a1, a2, a3, vb[nt][0], vb[nt][1]);
        }

        if (it < Sq / 64 - 1) { AT_STK(cur ^ 1); AT_STV(cur ^ 1); }
        __syncthreads();
    }

    // reduce row sums over the 4 lc lanes
    lsum0 += __shfl_xor_sync(0xffffffffu, lsum0, 1);
    lsum0 += __shfl_xor_sync(0xffffffffu, lsum0, 2);
    lsum1 += __shfl_xor_sync(0xffffffffu, lsum1, 1);
    lsum1 += __shfl_xor_sync(0xffffffffu, lsum1, 2);
    const float inv0 = 1.0f / lsum0, inv1 = 1.0f / lsum1;

    if (lc == 0) {
        g_linv[((size_t)(b * Sq + qg0)) * Hh + h]     = inv0;
        g_linv[((size_t)(b * Sq + qg0 + 8)) * Hh + h] = inv1;
    }

    // epilogue: write O (scaled, f16) to g_ao
    __half* orow0 = g_ao + (size_t)(b * Sq + qg0) * Dm + h * Dk;
    __half* orow1 = orow0 + 8 * Dm;
#pragma unroll
    for (int nt = 0; nt < 8; nt++) {
        int d = nt * 8 + lc * 2;
        *(__half2*)(orow0 + d) = __floats2half2_rn(o_acc[nt][0] * inv0, o_acc[nt][1] * inv0);
        *(__half2*)(orow1 + d) = __floats2half2_rn(o_acc[nt][2] * inv1, o_acc[nt][3] * inv1);
    }
#undef AT_LDK
#undef AT_STK
#undef AT_LDV
#undef AT_STV
}

// ============================================================================
// K3: normalize scores rows: sc[row][:] *= linv[row]. Pure streaming.
// ============================================================================
__global__ __launch_bounds__(512) void norm_rows(
    float* __restrict__ sc, const float* __restrict__ linv)
{
    const int r = blockIdx.x;
    const float s = linv[r];
    float4* p = (float4*)(sc + (size_t)r * Sq);
    float4 v = p[threadIdx.x];
    v.x *= s; v.y *= s; v.z *= s; v.w *= s;
    p[threadIdx.x] = v;
}

// ============================================================================
// K4: final projection out = g_ao(f16) @ Wo^T + bo  (fp16 mma)
// ============================================================================
__global__ __launch_bounds__(256) void outproj_tc(
    const float* __restrict__ W, const float* __restrict__ bias, float* __restrict__ C)
{
    __shared__ __half As[2][128][24];
    __shared__ __half Bs[2][128][24];
    const int tid = threadIdx.x;
    const int lane = tid & 31, wid = tid >> 5;
    const int wm = wid & 1, wn = wid >> 1;
    const int bm = blockIdx.y * 128, bn = blockIdx.x * 128;
    const int lr = lane >> 2, lc = lane & 3;
    const __half* __restrict__ A = g_ao;

    const int row0 = tid >> 1, seg = (tid & 1) * 8;

    const int a_row = lane & 15;
    const int a_cB  = ((lane >> 4) & 1) * 16;
    const int b_row = (lane & 7) + ((lane >> 3) & 1) * 8;
    const int b_cB  = ((lane >> 4) & 1) * 16;

    const uint32_t sA = s2u(&As[0][0][0]);
    const uint32_t sB = s2u(&Bs[0][0][0]);

    uint4 rau;
    float4 rb0, rb1;

#define OP_LD(k0) do { \
    rau = *(const uint4*)(A + (size_t)(bm + row0) * Dm + (k0) + seg); \
    rb0 = *(const float4*)(W + (size_t)(bn + row0) * Dm + (k0) + seg); \
    rb1 = *(const float4*)(W + (size_t)(bn + row0) * Dm + (k0) + seg + 4); \
} while (0)

#define OP_ST(st) do { \
    *(uint4*)&As[st][row0][seg] = rau; \
    *(uint4*)&Bs[st][row0][seg] = f8h(rb0, rb1); \
} while (0)

    float acc[4][4][4];
#pragma unroll
    for (int i = 0; i < 4; i++)
#pragma unroll
        for (int j = 0; j < 4; j++)
#pragma unroll
            for (int t = 0; t < 4; t++) acc[i][j][t] = 0.f;

    OP_LD(0); OP_ST(0); __syncthreads();

    for (int it = 0; it < 64; it++) {
        const int cur = it & 1;
        if (it < 63) OP_LD((it + 1) * 16);

        uint32_t af[4][4], bf[4][2];
#pragma unroll
        for (int mt = 0; mt < 4; mt++)
            ldsm_x4(af[mt][0], af[mt][1], af[mt][2], af[mt][3],
                sA + (cur * 128 + wm * 64 + mt * 16 + a_row) * 48 + a_cB);
#pragma unroll
        for (int ntp = 0; ntp < 2; ntp++) {
            uint32_t r0, r1, r2, r3;
            ldsm_x4(r0, r1, r2, r3,
                sB + (cur * 128 + wn * 32 + ntp * 16 + b_row) * 48 + b_cB);
            bf[2 * ntp][0] = r0; bf[2 * ntp][1] = r2;
            bf[2 * ntp + 1][0] = r1; bf[2 * ntp + 1][1] = r3;
        }
#pragma unroll
        for (int mt = 0; mt < 4; mt++)
#pragma unroll
            for (int nt = 0; nt < 4; nt++)
                mma_f16(acc[mt][nt], af[mt][0], af[mt][1], af[mt][2], af[mt][3],
                        bf[nt][0], bf[nt][1]);

        if (it < 63) OP_ST(cur ^ 1);
        __syncthreads();
    }

#pragma unroll
    for (int mt = 0; mt < 4; mt++) {
#pragma unroll
        for (int nt = 0; nt < 4; nt++) {
            int col = bn + wn * 32 + nt * 8 + lc * 2;
            float b0 = bias[col], b1 = bias[col + 1];
#pragma unroll
            for (int half = 0; half < 2; half++) {
                int m = bm + wm * 64 + mt * 16 + lr + half * 8;
                float2 v;
                v.x = acc[mt][nt][half * 2 + 0] + b0;
                v.y = acc[mt][nt][half * 2 + 1] + b1;
                *(float2*)(C + (size_t)m * Dm + col) = v;
            }
        }
    }
#undef OP_LD
#undef OP_ST
}

// ============================================================================
extern "C" void kernel_launch(void* const* d_in, const int* in_sizes, int n_in,
                              void* d_out, int out_size)
{
    const float* q    = (const float*)d_in[0];
    const float* k    = (const float*)d_in[1];
    const float* v    = (const float*)d_in[2];
    const int*   mask = (const int*)d_in[3];
    const float* Wq   = (const float*)d_in[4];
    const float* bq   = (const float*)d_in[5];
    const float* Wk   = (const float*)d_in[6];
    const float* bk   = (const float*)d_in[7];
    const float* Wv   = (const float*)d_in[8];
    const float* bv   = (const float*)d_in[9];
    const float* Wo   = (const float*)d_in[10];
    const float* bo   = (const float*)d_in[11];

    float* out = (float*)d_out;
    float* sc  = out + (size_t)Bb * Sq * Dm;   // scores_out region

    // attn smem: Qs 36864 + Ks 18432 + Vs 18432 + Ps 69632 = 143360 B
    const int attn_smem = 143360;
    cudaFuncSetAttribute(attn_fused, cudaFuncAttributeMaxDynamicSharedMemorySize, attn_smem);

    dim3 gp(Dm / 128, (Bb * Sq) / 128, 3);
    proj_tc<<<gp, 256>>>(q, k, v, Wq, Wk, Wv, bq, bk, bv);

    dim3 ga(Sq / QT, Bb * Hh);
    attn_fused<<<ga, 512, attn_smem>>>(mask, sc);

    float* linv_ptr;
    cudaGetSymbolAddress((void**)&linv_ptr, g_linv);
    norm_rows<<<Bb * Sq * Hh, 512>>>(sc, linv_ptr);

    dim3 go(Dm / 128, (Bb * Sq) / 128);
    outproj_tc<<<go, 256>>>(Wo, bo, out);
}

// round 12
// speedup vs baseline: 1.4393x; 1.1150x over previous
#include <cuda_runtime.h>
#include <cuda_fp16.h>
#include <cstdint>

#define Bb 2
#define Sq 2048
#define Dm 1024
#define Hh 16
#define Dk 64

// Scratch (allocation-free rule: __device__ globals) — f16 intermediates
__device__ __align__(16) __half g_qh[(size_t)Bb*Hh*Sq*Dk];
__device__ __align__(16) __half g_kh[(size_t)Bb*Hh*Sq*Dk];
__device__ __align__(16) __half g_vh[(size_t)Bb*Hh*Sq*Dk];
__device__ __align__(16) __half g_ao[(size_t)Bb*Sq*Dm];
__device__ __align__(16) float  g_linv[(size_t)Bb*Sq*Hh];
__device__ __align__(16) __half g_eh[(size_t)Bb*Sq*Hh*Sq];   // unnormalized exp(s), fp16

// ---------------------------------------------------------------------------
__device__ __forceinline__ uint32_t h2u(float a, float b) {
    __half2 h = __floats2half2_rn(a, b);
    return *(uint32_t*)&h;
}

__device__ __forceinline__ uint4 f8h(float4 a, float4 b) {
    uint4 r;
    r.x = h2u(a.x, a.y); r.y = h2u(a.z, a.w);
    r.z = h2u(b.x, b.y); r.w = h2u(b.z, b.w);
    return r;
}

__device__ __forceinline__ void mma_f16(float c[4],
    uint32_t a0, uint32_t a1, uint32_t a2, uint32_t a3,
    uint32_t b0, uint32_t b1)
{
    asm volatile(
        "mma.sync.aligned.m16n8k16.row.col.f32.f16.f16.f32 "
        "{%0,%1,%2,%3}, {%4,%5,%6,%7}, {%8,%9}, {%0,%1,%2,%3};"
        : "+f"(c[0]), "+f"(c[1]), "+f"(c[2]), "+f"(c[3])
        : "r"(a0), "r"(a1), "r"(a2), "r"(a3), "r"(b0), "r"(b1));
}

__device__ __forceinline__ void ldsm_x4(uint32_t& r0, uint32_t& r1,
                                        uint32_t& r2, uint32_t& r3, uint32_t addr)
{
    asm volatile("ldmatrix.sync.aligned.m8n8.x4.shared.b16 {%0,%1,%2,%3}, [%4];"
        : "=r"(r0), "=r"(r1), "=r"(r2), "=r"(r3) : "r"(addr));
}

__device__ __forceinline__ void ldsm_x4_t(uint32_t& r0, uint32_t& r1,
                                          uint32_t& r2, uint32_t& r3, uint32_t addr)
{
    asm volatile("ldmatrix.sync.aligned.m8n8.x4.trans.shared.b16 {%0,%1,%2,%3}, [%4];"
        : "=r"(r0), "=r"(r1), "=r"(r2), "=r"(r3) : "r"(addr));
}

__device__ __forceinline__ uint32_t s2u(const void* p) {
    return (uint32_t)__cvta_generic_to_shared(p);
}

// ============================================================================
// K1: fused Q/K/V projection, fp16 m16n8k16 (R11 proven).
// ============================================================================
__global__ __launch_bounds__(256) void proj_tc(
    const float* __restrict__ xq, const float* __restrict__ xk, const float* __restrict__ xv,
    const float* __restrict__ wq, const float* __restrict__ wk, const float* __restrict__ wv,
    const float* __restrict__ bq, const float* __restrict__ bk, const float* __restrict__ bv)
{
    const int which = blockIdx.z;
    const float* __restrict__ A    = which == 0 ? xq : (which == 1 ? xk : xv);
    const float* __restrict__ W    = which == 0 ? wq : (which == 1 ? wk : wv);
    const float* __restrict__ bias = which == 0 ? bq : (which == 1 ? bk : bv);
    __half* __restrict__ dst       = which == 0 ? g_qh : (which == 1 ? g_kh : g_vh);

    __shared__ __half As[2][128][24];
    __shared__ __half Bs[2][128][24];

    const int tid = threadIdx.x;
    const int lane = tid & 31, wid = tid >> 5;
    const int wm = wid & 1, wn = wid >> 1;
    const int bm = blockIdx.y * 128, bn = blockIdx.x * 128;
    const int lr = lane >> 2, lc = lane & 3;

    const int row0 = tid >> 1, seg = (tid & 1) * 8;

    const int a_row = lane & 15;
    const int a_cB  = ((lane >> 4) & 1) * 16;
    const int b_row = (lane & 7) + ((lane >> 3) & 1) * 8;
    const int b_cB  = ((lane >> 4) & 1) * 16;

    const uint32_t sA = s2u(&As[0][0][0]);
    const uint32_t sB = s2u(&Bs[0][0][0]);

    float4 ra0, ra1, rb0, rb1;

#define PJ_LD(k0) do { \
    ra0 = *(const float4*)(A + (size_t)(bm + row0) * Dm + (k0) + seg); \
    ra1 = *(const float4*)(A + (size_t)(bm + row0) * Dm + (k0) + seg + 4); \
    rb0 = *(const float4*)(W + (size_t)(bn + row0) * Dm + (k0) + seg); \
    rb1 = *(const float4*)(W + (size_t)(bn + row0) * Dm + (k0) + seg + 4); \
} while (0)

#define PJ_ST(st) do { \
    *(uint4*)&As[st][row0][seg] = f8h(ra0, ra1); \
    *(uint4*)&Bs[st][row0][seg] = f8h(rb0, rb1); \
} while (0)

    float acc[4][4][4];
#pragma unroll
    for (int i = 0; i < 4; i++)
#pragma unroll
        for (int j = 0; j < 4; j++)
#pragma unroll
            for (int t = 0; t < 4; t++) acc[i][j][t] = 0.f;

    PJ_LD(0); PJ_ST(0); __syncthreads();

    for (int it = 0; it < 64; it++) {
        const int cur = it & 1;
        if (it < 63) PJ_LD((it + 1) * 16);

        uint32_t af[4][4], bf[4][2];
#pragma unroll
        for (int mt = 0; mt < 4; mt++)
            ldsm_x4(af[mt][0], af[mt][1], af[mt][2], af[mt][3],
                sA + (cur * 128 + wm * 64 + mt * 16 + a_row) * 48 + a_cB);
#pragma unroll
        for (int ntp = 0; ntp < 2; ntp++) {
            uint32_t r0, r1, r2, r3;
            ldsm_x4(r0, r1, r2, r3,
                sB + (cur * 128 + wn * 32 + ntp * 16 + b_row) * 48 + b_cB);
            bf[2 * ntp][0] = r0; bf[2 * ntp][1] = r2;
            bf[2 * ntp + 1][0] = r1; bf[2 * ntp + 1][1] = r3;
        }
#pragma unroll
        for (int mt = 0; mt < 4; mt++)
#pragma unroll
            for (int nt = 0; nt < 4; nt++)
                mma_f16(acc[mt][nt], af[mt][0], af[mt][1], af[mt][2], af[mt][3],
                        bf[nt][0], bf[nt][1]);

        if (it < 63) PJ_ST(cur ^ 1);
        __syncthreads();
    }

#pragma unroll
    for (int mt = 0; mt < 4; mt++) {
#pragma unroll
        for (int nt = 0; nt < 4; nt++) {
            int col = bn + wn * 32 + nt * 8 + lc * 2;
            int h = col >> 6, d = col & 63;
            float b0 = bias[col], b1 = bias[col + 1];
#pragma unroll
            for (int half = 0; half < 2; half++) {
                int m = bm + wm * 64 + mt * 16 + lr + half * 8;
                int b = m >> 11;
                int s = m & (Sq - 1);
                __half2 hv = __floats2half2_rn(acc[mt][nt][half * 2 + 0] + b0,
                                               acc[mt][nt][half * 2 + 1] + b1);
                *(__half2*)(dst + (((size_t)(b * Hh + h) * Sq + s) << 6) + d) = hv;
            }
        }
    }
#undef PJ_LD
#undef PJ_ST
}

// ============================================================================
// K2: fused attention, single pass (fp16 mma). E written fp16 to g_eh;
// 1/rowsum to g_linv; norm kernel produces final fp32 scores.
// ============================================================================
#define QT 256

__global__ __launch_bounds__(512, 1) void attn_fused(const int* __restrict__ mask)
{
    extern __shared__ char shb[];
    __half (*Qs)[72]     = (__half(*)[72])shb;                  // [q256][d]
    __half (*Ks)[64][72] = (__half(*)[64][72])(shb + 36864);    // [st][tok][d]
    __half (*Vs)[64][72] = (__half(*)[64][72])(shb + 55296);    // [st][tok][d]
    __half (*Ps)[72]     = (__half(*)[72])(shb + 73728);        // [q][k] fp16 staging

    const int bh = blockIdx.y;
    const int b = bh >> 4, h = bh & 15;
    const int q0 = blockIdx.x * QT;
    const __half* qp    = g_qh + ((size_t)bh * Sq + q0) * Dk;
    const __half* kbase = g_kh + (size_t)bh * Sq * Dk;
    const __half* vbase = g_vh + (size_t)bh * Sq * Dk;

    const int tid = threadIdx.x;
    const int lane = tid & 31, w = tid >> 5;          // 16 warps
    const int lr = lane >> 2, lc = lane & 3;
    const int r0 = 16 * w + lr;
    const int qg0 = q0 + r0;

    const int a_row = lane & 15;
    const int a_cB  = ((lane >> 4) & 1) * 16;
    const int b_row = (lane & 7) + ((lane >> 3) & 1) * 8;
    const int b_cB  = ((lane >> 4) & 1) * 16;

    const uint32_t sQ = s2u(&Qs[0][0]);
    const uint32_t sK = s2u(&Ks[0][0][0]);
    const uint32_t sV = s2u(&Vs[0][0][0]);

    const int rA = tid >> 3, segA = (tid & 7) * 8;

    uint4 rk, rv;

#define AT_LDK(kt) rk = *(const uint4*)(kbase + (size_t)((kt) + rA) * Dk + segA)
#define AT_STK(st) *(uint4*)&Ks[st][rA][segA] = rk
#define AT_LDV(kt) rv = *(const uint4*)(vbase + (size_t)((kt) + rA) * Dk + segA)
#define AT_STV(st) *(uint4*)&Vs[st][rA][segA] = rv

#pragma unroll
    for (int t = 0; t < 4; t++) {
        int f = tid + t * 512;
        int row = f >> 3;
        int sg = (f & 7) * 8;
        *(uint4*)&Qs[row][sg] = *(const uint4*)(qp + row * Dk + sg);
    }

    const int* mrow0 = mask + ((size_t)b * Sq + qg0) * Sq;
    const int* mrow1 = mrow0 + 8 * Sq;

    float lsum0 = 0.f, lsum1 = 0.f;
    float o_acc[8][4];
#pragma unroll
    for (int nt = 0; nt < 8; nt++)
#pragma unroll
        for (int e = 0; e < 4; e++) o_acc[nt][e] = 0.f;

    AT_LDK(0); AT_LDV(0); AT_STK(0); AT_STV(0); __syncthreads();

    for (int it = 0; it < Sq / 64; it++) {
        const int cur = it & 1;
        const int kt = it * 64;
        if (it < Sq / 64 - 1) { AT_LDK(kt + 64); AT_LDV(kt + 64); }

        float acc[8][4];
#pragma unroll
        for (int nt = 0; nt < 8; nt++)
#pragma unroll
            for (int e = 0; e < 4; e++) acc[nt][e] = 0.f;

        // ---- QK^T: 4 k16-groups over d ----
#pragma unroll
        for (int g = 0; g < 4; g++) {
            uint32_t qa[4], kb[8][2];
            ldsm_x4(qa[0], qa[1], qa[2], qa[3],
                sQ + (16 * w + a_row) * 144 + g * 32 + a_cB);
#pragma unroll
            for (int ntp = 0; ntp < 4; ntp++) {
                uint32_t r0u, r1u, r2u, r3u;
                ldsm_x4(r0u, r1u, r2u, r3u,
                    sK + (cur * 64 + ntp * 16 + b_row) * 144 + g * 32 + b_cB);
                kb[2 * ntp][0] = r0u; kb[2 * ntp][1] = r2u;
                kb[2 * ntp + 1][0] = r1u; kb[2 * ntp + 1][1] = r3u;
            }
#pragma unroll
            for (int nt = 0; nt < 8; nt++)
                mma_f16(acc[nt], qa[0], qa[1], qa[2], qa[3], kb[nt][0], kb[nt][1]);
        }

        // ---- exp (no max), mask -> 0, row sums; stage fp16 into Ps ----
#pragma unroll
        for (int nt = 0; nt < 8; nt++) {
            int kc = kt + nt * 8 + lc * 2;
            int2 ma = *(const int2*)(mrow0 + kc);
            int2 mb = *(const int2*)(mrow1 + kc);
            float e00 = (ma.x == 0) ? 0.f : __expf(acc[nt][0] * 0.125f);
            float e01 = (ma.y == 0) ? 0.f : __expf(acc[nt][1] * 0.125f);
            float e10 = (mb.x == 0) ? 0.f : __expf(acc[nt][2] * 0.125f);
            float e11 = (mb.y == 0) ? 0.f : __expf(acc[nt][3] * 0.125f);
            lsum0 += e00 + e01;
            lsum1 += e10 + e11;
            acc[nt][0] = e00; acc[nt][1] = e01;
            acc[nt][2] = e10; acc[nt][3] = e11;
            int cl = nt * 8 + lc * 2;
            *(__half2*)&Ps[r0][cl]     = __floats2half2_rn(e00, e01);
            *(__half2*)&Ps[r0 + 8][cl] = __floats2half2_rn(e10, e11);
        }
        __syncthreads();

        // coalesced write of unnormalized E tile (256 rows x 64 cols, fp16)
#pragma unroll
        for (int t = 0; t < 4; t++) {
            int f = tid + t * 512;
            int row = f >> 3;
            int sg = (f & 7) * 8;
            uint4 v = *(const uint4*)&Ps[row][sg];
            *(uint4*)(g_eh + (((size_t)(b * Sq + q0 + row)) * Hh + h) * Sq + kt + sg) = v;
        }

        // ---- O += E @ V: A from registers, B via ldsm.trans
#pragma unroll
        for (int g = 0; g < 4; g++) {
            uint32_t a0 = h2u(acc[2 * g][0],     acc[2 * g][1]);
            uint32_t a1 = h2u(acc[2 * g][2],     acc[2 * g][3]);
            uint32_t a2 = h2u(acc[2 * g + 1][0], acc[2 * g + 1][1]);
            uint32_t a3 = h2u(acc[2 * g + 1][2], acc[2 * g + 1][3]);
            uint32_t vb[8][2];
#pragma unroll
            for (int ntp = 0; ntp < 4; ntp++) {
                uint32_t r0u, r1u, r2u, r3u;
                ldsm_x4_t(r0u, r1u, r2u, r3u,
                    sV + (cur * 64 + g * 16 + b_row) * 144 + ntp * 32 + b_cB);
                vb[2 * ntp][0] = r0u; vb[2 * ntp][1] = r1u;
                vb[2 * ntp + 1][0] = r2u; vb[2 * ntp + 1][1] = r3u;
            }
#pragma unroll
            for (int nt = 0; nt < 8; nt++)
                mma_f16(o_acc[nt], a0, a1, a2, a3, vb[nt][0], vb[nt][1]);
        }

        if (it < Sq / 64 - 1) { AT_STK(cur ^ 1); AT_STV(cur ^ 1); }
        __syncthreads();
    }

    // reduce row sums over the 4 lc lanes
    lsum0 += __shfl_xor_sync(0xffffffffu, lsum0, 1);
    lsum0 += __shfl_xor_sync(0xffffffffu, lsum0, 2);
    lsum1 += __shfl_xor_sync(0xffffffffu, lsum1, 1);
    lsum1 += __shfl_xor_sync(0xffffffffu, lsum1, 2);
    const float inv0 = 1.0f / lsum0, inv1 = 1.0f / lsum1;

    if (lc == 0) {
        g_linv[((size_t)(b * Sq + qg0)) * Hh + h]     = inv0;
        g_linv[((size_t)(b * Sq + qg0 + 8)) * Hh + h] = inv1;
    }

    // epilogue: write O (scaled, f16) to g_ao
    __half* orow0 = g_ao + (size_t)(b * Sq + qg0) * Dm + h * Dk;
    __half* orow1 = orow0 + 8 * Dm;
#pragma unroll
    for (int nt = 0; nt < 8; nt++) {
        int d = nt * 8 + lc * 2;
        *(__half2*)(orow0 + d) = __floats2half2_rn(o_acc[nt][0] * inv0, o_acc[nt][1] * inv0);
        *(__half2*)(orow1 + d) = __floats2half2_rn(o_acc[nt][2] * inv1, o_acc[nt][3] * inv1);
    }
#undef AT_LDK
#undef AT_STK
#undef AT_LDV
#undef AT_STV
}

// ============================================================================
// K3: normalize: sc[row][:] = fp32(eh[row][:]) * linv[row].  780MB streaming.
// ============================================================================
__global__ __launch_bounds__(512) void norm_rows(
    float* __restrict__ sc, const __half* __restrict__ eh,
    const float* __restrict__ linv)
{
    const int r = blockIdx.x;
    const float s = linv[r];
    uint2 u = ((const uint2*)(eh + (size_t)r * Sq))[threadIdx.x];
    __half2 h0 = *(__half2*)&u.x;
    __half2 h1 = *(__half2*)&u.y;
    float2 f0 = __half22float2(h0);
    float2 f1 = __half22float2(h1);
    float4 v;
    v.x = f0.x * s; v.y = f0.y * s;
    v.z = f1.x * s; v.w = f1.y * s;
    ((float4*)(sc + (size_t)r * Sq))[threadIdx.x] = v;
}

// ============================================================================
// K4: final projection out = g_ao(f16) @ Wo^T + bo  (fp16 mma, R11 proven)
// ============================================================================
__global__ __launch_bounds__(256) void outproj_tc(
    const float* __restrict__ W, const float* __restrict__ bias, float* __restrict__ C)
{
    __shared__ __half As[2][128][24];
    __shared__ __half Bs[2][128][24];
    const int tid = threadIdx.x;
    const int lane = tid & 31, wid = tid >> 5;
    const int wm = wid & 1, wn = wid >> 1;
    const int bm = blockIdx.y * 128, bn = blockIdx.x * 128;
    const int lr = lane >> 2, lc = lane & 3;
    const __half* __restrict__ A = g_ao;

    const int row0 = tid >> 1, seg = (tid & 1) * 8;

    const int a_row = lane & 15;
    const int a_cB  = ((lane >> 4) & 1) * 16;
    const int b_row = (lane & 7) + ((lane >> 3) & 1) * 8;
    const int b_cB  = ((lane >> 4) & 1) * 16;

    const uint32_t sA = s2u(&As[0][0][0]);
    const uint32_t sB = s2u(&Bs[0][0][0]);

    uint4 rau;
    float4 rb0, rb1;

#define OP_LD(k0) do { \
    rau = *(const uint4*)(A + (size_t)(bm + row0) * Dm + (k0) + seg); \
    rb0 = *(const float4*)(W + (size_t)(bn + row0) * Dm + (k0) + seg); \
    rb1 = *(const float4*)(W + (size_t)(bn + row0) * Dm + (k0) + seg + 4); \
} while (0)

#define OP_ST(st) do { \
    *(uint4*)&As[st][row0][seg] = rau; \
    *(uint4*)&Bs[st][row0][seg] = f8h(rb0, rb1); \
} while (0)

    float acc[4][4][4];
#pragma unroll
    for (int i = 0; i < 4; i++)
#pragma unroll
        for (int j = 0; j < 4; j++)
#pragma unroll
            for (int t = 0; t < 4; t++) acc[i][j][t] = 0.f;

    OP_LD(0); OP_ST(0); __syncthreads();

    for (int it = 0; it < 64; it++) {
        const int cur = it & 1;
        if (it < 63) OP_LD((it + 1) * 16);

        uint32_t af[4][4], bf[4][2];
#pragma unroll
        for (int mt = 0; mt < 4; mt++)
            ldsm_x4(af[mt][0], af[mt][1], af[mt][2], af[mt][3],
                sA + (cur * 128 + wm * 64 + mt * 16 + a_row) * 48 + a_cB);
#pragma unroll
        for (int ntp = 0; ntp < 2; ntp++) {
            uint32_t r0, r1, r2, r3;
            ldsm_x4(r0, r1, r2, r3,
                sB + (cur * 128 + wn * 32 + ntp * 16 + b_row) * 48 + b_cB);
            bf[2 * ntp][0] = r0; bf[2 * ntp][1] = r2;
            bf[2 * ntp + 1][0] = r1; bf[2 * ntp + 1][1] = r3;
        }
#pragma unroll
        for (int mt = 0; mt < 4; mt++)
#pragma unroll
            for (int nt = 0; nt < 4; nt++)
                mma_f16(acc[mt][nt], af[mt][0], af[mt][1], af[mt][2], af[mt][3],
                        bf[nt][0], bf[nt][1]);

        if (it < 63) OP_ST(cur ^ 1);
        __syncthreads();
    }

#pragma unroll
    for (int mt = 0; mt < 4; mt++) {
#pragma unroll
        for (int nt = 0; nt < 4; nt++) {
            int col = bn + wn * 32 + nt * 8 + lc * 2;
            float b0 = bias[col], b1 = bias[col + 1];
#pragma unroll
            for (int half = 0; half < 2; half++) {
                int m = bm + wm * 64 + mt * 16 + lr + half * 8;
                float2 v;
                v.x = acc[mt][nt][half * 2 + 0] + b0;
                v.y = acc[mt][nt][half * 2 + 1] + b1;
                *(float2*)(C + (size_t)m * Dm + col) = v;
            }
        }
    }
#undef OP_LD
#undef OP_ST
}

// ============================================================================
extern "C" void kernel_launch(void* const* d_in, const int* in_sizes, int n_in,
                              void* d_out, int out_size)
{
    const float* q    = (const float*)d_in[0];
    const float* k    = (const float*)d_in[1];
    const float* v    = (const float*)d_in[2];
    const int*   mask = (const int*)d_in[3];
    const float* Wq   = (const float*)d_in[4];
    const float* bq   = (const float*)d_in[5];
    const float* Wk   = (const float*)d_in[6];
    const float* bk   = (const float*)d_in[7];
    const float* Wv   = (const float*)d_in[8];
    const float* bv   = (const float*)d_in[9];
    const float* Wo   = (const float*)d_in[10];
    const float* bo   = (const float*)d_in[11];

    float* out = (float*)d_out;
    float* sc  = out + (size_t)Bb * Sq * Dm;   // scores_out region

    // attn smem: Qs 36864 + Ks 18432 + Vs 18432 + Ps 36864 = 110592 B
    const int attn_smem = 110592;
    cudaFuncSetAttribute(attn_fused, cudaFuncAttributeMaxDynamicSharedMemorySize, attn_smem);

    dim3 gp(Dm / 128, (Bb * Sq) / 128, 3);
    proj_tc<<<gp, 256>>>(q, k, v, Wq, Wk, Wv, bq, bk, bv);

    dim3 ga(Sq / QT, Bb * Hh);
    attn_fused<<<ga, 512, attn_smem>>>(mask);

    float* linv_ptr;
    __half* eh_ptr;
    cudaGetSymbolAddress((void**)&linv_ptr, g_linv);
    cudaGetSymbolAddress((void**)&eh_ptr,  g_eh);
    norm_rows<<<Bb * Sq * Hh, 512>>>(sc, eh_ptr, linv_ptr);

    dim3 go(Dm / 128, (Bb * Sq) / 128);
    outproj_tc<<<go, 256>>>(Wo, bo, out);
}

// round 13
// speedup vs baseline: 1.4413x; 1.0014x over previous
#include <cuda_runtime.h>
#include <cuda_fp16.h>
#include <cstdint>

#define Bb 2
#define Sq 2048
#define Dm 1024
#define Hh 16
#define Dk 64

// Scratch (allocation-free rule: __device__ globals) — f16 intermediates
__device__ __align__(16) __half g_qh[(size_t)Bb*Hh*Sq*Dk];
__device__ __align__(16) __half g_kh[(size_t)Bb*Hh*Sq*Dk];
__device__ __align__(16) __half g_vh[(size_t)Bb*Hh*Sq*Dk];
__device__ __align__(16) __half g_ao[(size_t)Bb*Sq*Dm];
__device__ __align__(16) float  g_linv[(size_t)Bb*Sq*Hh];
__device__ __align__(16) __half g_eh[(size_t)Bb*Sq*Hh*Sq];   // unnormalized exp(s), fp16

// ---------------------------------------------------------------------------
__device__ __forceinline__ uint32_t h2u(float a, float b) {
    __half2 h = __floats2half2_rn(a, b);
    return *(uint32_t*)&h;
}

__device__ __forceinline__ uint4 f8h(float4 a, float4 b) {
    uint4 r;
    r.x = h2u(a.x, a.y); r.y = h2u(a.z, a.w);
    r.z = h2u(b.x, b.y); r.w = h2u(b.z, b.w);
    return r;
}

__device__ __forceinline__ void mma_f16(float c[4],
    uint32_t a0, uint32_t a1, uint32_t a2, uint32_t a3,
    uint32_t b0, uint32_t b1)
{
    asm volatile(
        "mma.sync.aligned.m16n8k16.row.col.f32.f16.f16.f32 "
        "{%0,%1,%2,%3}, {%4,%5,%6,%7}, {%8,%9}, {%0,%1,%2,%3};"
        : "+f"(c[0]), "+f"(c[1]), "+f"(c[2]), "+f"(c[3])
        : "r"(a0), "r"(a1), "r"(a2), "r"(a3), "r"(b0), "r"(b1));
}

__device__ __forceinline__ void ldsm_x4(uint32_t& r0, uint32_t& r1,
                                        uint32_t& r2, uint32_t& r3, uint32_t addr)
{
    asm volatile("ldmatrix.sync.aligned.m8n8.x4.shared.b16 {%0,%1,%2,%3}, [%4];"
        : "=r"(r0), "=r"(r1), "=r"(r2), "=r"(r3) : "r"(addr));
}

__device__ __forceinline__ void ldsm_x4_t(uint32_t& r0, uint32_t& r1,
                                          uint32_t& r2, uint32_t& r3, uint32_t addr)
{
    asm volatile("ldmatrix.sync.aligned.m8n8.x4.trans.shared.b16 {%0,%1,%2,%3}, [%4];"
        : "=r"(r0), "=r"(r1), "=r"(r2), "=r"(r3) : "r"(addr));
}

__device__ __forceinline__ uint32_t s2u(const void* p) {
    return (uint32_t)__cvta_generic_to_shared(p);
}

// ============================================================================
// K1: fused Q/K/V projection, fp16 m16n8k16 (R11 proven).
// ============================================================================
__global__ __launch_bounds__(256) void proj_tc(
    const float* __restrict__ xq, const float* __restrict__ xk, const float* __restrict__ xv,
    const float* __restrict__ wq, const float* __restrict__ wk, const float* __restrict__ wv,
    const float* __restrict__ bq, const float* __restrict__ bk, const float* __restrict__ bv)
{
    const int which = blockIdx.z;
    const float* __restrict__ A    = which == 0 ? xq : (which == 1 ? xk : xv);
    const float* __restrict__ W    = which == 0 ? wq : (which == 1 ? wk : wv);
    const float* __restrict__ bias = which == 0 ? bq : (which == 1 ? bk : bv);
    __half* __restrict__ dst       = which == 0 ? g_qh : (which == 1 ? g_kh : g_vh);

    __shared__ __half As[2][128][24];
    __shared__ __half Bs[2][128][24];

    const int tid = threadIdx.x;
    const int lane = tid & 31, wid = tid >> 5;
    const int wm = wid & 1, wn = wid >> 1;
    const int bm = blockIdx.y * 128, bn = blockIdx.x * 128;
    const int lr = lane >> 2, lc = lane & 3;

    const int row0 = tid >> 1, seg = (tid & 1) * 8;

    const int a_row = lane & 15;
    const int a_cB  = ((lane >> 4) & 1) * 16;
    const int b_row = (lane & 7) + ((lane >> 3) & 1) * 8;
    const int b_cB  = ((lane >> 4) & 1) * 16;

    const uint32_t sA = s2u(&As[0][0][0]);
    const uint32_t sB = s2u(&Bs[0][0][0]);

    float4 ra0, ra1, rb0, rb1;

#define PJ_LD(k0) do { \
    ra0 = *(const float4*)(A + (size_t)(bm + row0) * Dm + (k0) + seg); \
    ra1 = *(const float4*)(A + (size_t)(bm + row0) * Dm + (k0) + seg + 4); \
    rb0 = *(const float4*)(W + (size_t)(bn + row0) * Dm + (k0) + seg); \
    rb1 = *(const float4*)(W + (size_t)(bn + row0) * Dm + (k0) + seg + 4); \
} while (0)

#define PJ_ST(st) do { \
    *(uint4*)&As[st][row0][seg] = f8h(ra0, ra1); \
    *(uint4*)&Bs[st][row0][seg] = f8h(rb0, rb1); \
} while (0)

    float acc[4][4][4];
#pragma unroll
    for (int i = 0; i < 4; i++)
#pragma unroll
        for (int j = 0; j < 4; j++)
#pragma unroll
            for (int t = 0; t < 4; t++) acc[i][j][t] = 0.f;

    PJ_LD(0); PJ_ST(0); __syncthreads();

    for (int it = 0; it < 64; it++) {
        const int cur = it & 1;
        if (it < 63) PJ_LD((it + 1) * 16);

        uint32_t af[4][4], bf[4][2];
#pragma unroll
        for (int mt = 0; mt < 4; mt++)
            ldsm_x4(af[mt][0], af[mt][1], af[mt][2], af[mt][3],
                sA + (cur * 128 + wm * 64 + mt * 16 + a_row) * 48 + a_cB);
#pragma unroll
        for (int ntp = 0; ntp < 2; ntp++) {
            uint32_t r0, r1, r2, r3;
            ldsm_x4(r0, r1, r2, r3,
                sB + (cur * 128 + wn * 32 + ntp * 16 + b_row) * 48 + b_cB);
            bf[2 * ntp][0] = r0; bf[2 * ntp][1] = r2;
            bf[2 * ntp + 1][0] = r1; bf[2 * ntp + 1][1] = r3;
        }
#pragma unroll
        for (int mt = 0; mt < 4; mt++)
#pragma unroll
            for (int nt = 0; nt < 4; nt++)
                mma_f16(acc[mt][nt], af[mt][0], af[mt][1], af[mt][2], af[mt][3],
                        bf[nt][0], bf[nt][1]);

        if (it < 63) PJ_ST(cur ^ 1);
        __syncthreads();
    }

#pragma unroll
    for (int mt = 0; mt < 4; mt++) {
#pragma unroll
        for (int nt = 0; nt < 4; nt++) {
            int col = bn + wn * 32 + nt * 8 + lc * 2;
            int h = col >> 6, d = col & 63;
            float b0 = bias[col], b1 = bias[col + 1];
#pragma unroll
            for (int half = 0; half < 2; half++) {
                int m = bm + wm * 64 + mt * 16 + lr + half * 8;
                int b = m >> 11;
                int s = m & (Sq - 1);
                __half2 hv = __floats2half2_rn(acc[mt][nt][half * 2 + 0] + b0,
                                               acc[mt][nt][half * 2 + 1] + b1);
                *(__half2*)(dst + (((size_t)(b * Hh + h) * Sq + s) << 6) + d) = hv;
            }
        }
    }
#undef PJ_LD
#undef PJ_ST
}

// ============================================================================
// K2: fused attention, single pass (fp16 mma). E written fp16 to g_eh;
// 1/rowsum to g_linv; norm kernel produces final fp32 scores.
// ============================================================================
#define QT 256

__global__ __launch_bounds__(512, 1) void attn_fused(const int* __restrict__ mask)
{
    extern __shared__ char shb[];
    __half (*Qs)[72]     = (__half(*)[72])shb;                  // [q256][d]
    __half (*Ks)[64][72] = (__half(*)[64][72])(shb + 36864);    // [st][tok][d]
    __half (*Vs)[64][72] = (__half(*)[64][72])(shb + 55296);    // [st][tok][d]
    __half (*Ps)[72]     = (__half(*)[72])(shb + 73728);        // [q][k] fp16 staging

    const int bh = blockIdx.y;
    const int b = bh >> 4, h = bh & 15;
    const int q0 = blockIdx.x * QT;
    const __half* qp    = g_qh + ((size_t)bh * Sq + q0) * Dk;
    const __half* kbase = g_kh + (size_t)bh * Sq * Dk;
    const __half* vbase = g_vh + (size_t)bh * Sq * Dk;

    const int tid = threadIdx.x;
    const int lane = tid & 31, w = tid >> 5;          // 16 warps
    const int lr = lane >> 2, lc = lane & 3;
    const int r0 = 16 * w + lr;
    const int qg0 = q0 + r0;

    const int a_row = lane & 15;
    const int a_cB  = ((lane >> 4) & 1) * 16;
    const int b_row = (lane & 7) + ((lane >> 3) & 1) * 8;
    const int b_cB  = ((lane >> 4) & 1) * 16;

    const uint32_t sQ = s2u(&Qs[0][0]);
    const uint32_t sK = s2u(&Ks[0][0][0]);
    const uint32_t sV = s2u(&Vs[0][0][0]);

    const int rA = tid >> 3, segA = (tid & 7) * 8;

    uint4 rk, rv;

#define AT_LDK(kt) rk = *(const uint4*)(kbase + (size_t)((kt) + rA) * Dk + segA)
#define AT_STK(st) *(uint4*)&Ks[st][rA][segA] = rk
#define AT_LDV(kt) rv = *(const uint4*)(vbase + (size_t)((kt) + rA) * Dk + segA)
#define AT_STV(st) *(uint4*)&Vs[st][rA][segA] = rv

#pragma unroll
    for (int t = 0; t < 4; t++) {
        int f = tid + t * 512;
        int row = f >> 3;
        int sg = (f & 7) * 8;
        *(uint4*)&Qs[row][sg] = *(const uint4*)(qp + row * Dk + sg);
    }

    const int* mrow0 = mask + ((size_t)b * Sq + qg0) * Sq;
    const int* mrow1 = mrow0 + 8 * Sq;

    float lsum0 = 0.f, lsum1 = 0.f;
    float o_acc[8][4];
#pragma unroll
    for (int nt = 0; nt < 8; nt++)
#pragma unroll
        for (int e = 0; e < 4; e++) o_acc[nt][e] = 0.f;

    AT_LDK(0); AT_LDV(0); AT_STK(0); AT_STV(0); __syncthreads();

    for (int it = 0; it < Sq / 64; it++) {
        const int cur = it & 1;
        const int kt = it * 64;
        if (it < Sq / 64 - 1) { AT_LDK(kt + 64); AT_LDV(kt + 64); }

        float acc[8][4];
#pragma unroll
        for (int nt = 0; nt < 8; nt++)
#pragma unroll
            for (int e = 0; e < 4; e++) acc[nt][e] = 0.f;

        // ---- QK^T: 4 k16-groups over d ----
#pragma unroll
        for (int g = 0; g < 4; g++) {
            uint32_t qa[4], kb[8][2];
            ldsm_x4(qa[0], qa[1], qa[2], qa[3],
                sQ + (16 * w + a_row) * 144 + g * 32 + a_cB);
#pragma unroll
            for (int ntp = 0; ntp < 4; ntp++) {
                uint32_t r0u, r1u, r2u, r3u;
                ldsm_x4(r0u, r1u, r2u, r3u,
                    sK + (cur * 64 + ntp * 16 + b_row) * 144 + g * 32 + b_cB);
                kb[2 * ntp][0] = r0u; kb[2 * ntp][1] = r2u;
                kb[2 * ntp + 1][0] = r1u; kb[2 * ntp + 1][1] = r3u;
            }
#pragma unroll
            for (int nt = 0; nt < 8; nt++)
                mma_f16(acc[nt], qa[0], qa[1], qa[2], qa[3], kb[nt][0], kb[nt][1]);
        }

        // ---- exp (no max), mask -> 0, row sums; stage fp16 into Ps ----
#pragma unroll
        for (int nt = 0; nt < 8; nt++) {
            int kc = kt + nt * 8 + lc * 2;
            int2 ma = *(const int2*)(mrow0 + kc);
            int2 mb = *(const int2*)(mrow1 + kc);
            float e00 = (ma.x == 0) ? 0.f : __expf(acc[nt][0] * 0.125f);
            float e01 = (ma.y == 0) ? 0.f : __expf(acc[nt][1] * 0.125f);
            float e10 = (mb.x == 0) ? 0.f : __expf(acc[nt][2] * 0.125f);
            float e11 = (mb.y == 0) ? 0.f : __expf(acc[nt][3] * 0.125f);
            lsum0 += e00 + e01;
            lsum1 += e10 + e11;
            acc[nt][0] = e00; acc[nt][1] = e01;
            acc[nt][2] = e10; acc[nt][3] = e11;
            int cl = nt * 8 + lc * 2;
            *(__half2*)&Ps[r0][cl]     = __floats2half2_rn(e00, e01);
            *(__half2*)&Ps[r0 + 8][cl] = __floats2half2_rn(e10, e11);
        }
        __syncthreads();

        // coalesced write of unnormalized E tile (256 rows x 64 cols, fp16)
#pragma unroll
        for (int t = 0; t < 4; t++) {
            int f = tid + t * 512;
            int row = f >> 3;
            int sg = (f & 7) * 8;
            uint4 v = *(const uint4*)&Ps[row][sg];
            *(uint4*)(g_eh + (((size_t)(b * Sq + q0 + row)) * Hh + h) * Sq + kt + sg) = v;
        }

        // ---- O += E @ V: A from registers, B via ldsm.trans
#pragma unroll
        for (int g = 0; g < 4; g++) {
            uint32_t a0 = h2u(acc[2 * g][0],     acc[2 * g][1]);
            uint32_t a1 = h2u(acc[2 * g][2],     acc[2 * g][3]);
            uint32_t a2 = h2u(acc[2 * g + 1][0], acc[2 * g + 1][1]);
            uint32_t a3 = h2u(acc[2 * g + 1][2], acc[2 * g + 1][3]);
            uint32_t vb[8][2];
#pragma unroll
            for (int ntp = 0; ntp < 4; ntp++) {
                uint32_t r0u, r1u, r2u, r3u;
                ldsm_x4_t(r0u, r1u, r2u, r3u,
                    sV + (cur * 64 + g * 16 + b_row) * 144 + ntp * 32 + b_cB);
                vb[2 * ntp][0] = r0u; vb[2 * ntp][1] = r1u;
                vb[2 * ntp + 1][0] = r2u; vb[2 * ntp + 1][1] = r3u;
            }
#pragma unroll
            for (int nt = 0; nt < 8; nt++)
                mma_f16(o_acc[nt], a0, a1, a2, a3, vb[nt][0], vb[nt][1]);
        }

        if (it < Sq / 64 - 1) { AT_STK(cur ^ 1); AT_STV(cur ^ 1); }
        __syncthreads();
    }

    // reduce row sums over the 4 lc lanes
    lsum0 += __shfl_xor_sync(0xffffffffu, lsum0, 1);
    lsum0 += __shfl_xor_sync(0xffffffffu, lsum0, 2);
    lsum1 += __shfl_xor_sync(0xffffffffu, lsum1, 1);
    lsum1 += __shfl_xor_sync(0xffffffffu, lsum1, 2);
    const float inv0 = 1.0f / lsum0, inv1 = 1.0f / lsum1;

    if (lc == 0) {
        g_linv[((size_t)(b * Sq + qg0)) * Hh + h]     = inv0;
        g_linv[((size_t)(b * Sq + qg0 + 8)) * Hh + h] = inv1;
    }

    // epilogue: write O (scaled, f16) to g_ao
    __half* orow0 = g_ao + (size_t)(b * Sq + qg0) * Dm + h * Dk;
    __half* orow1 = orow0 + 8 * Dm;
#pragma unroll
    for (int nt = 0; nt < 8; nt++) {
        int d = nt * 8 + lc * 2;
        *(__half2*)(orow0 + d) = __floats2half2_rn(o_acc[nt][0] * inv0, o_acc[nt][1] * inv0);
        *(__half2*)(orow1 + d) = __floats2half2_rn(o_acc[nt][2] * inv1, o_acc[nt][3] * inv1);
    }
#undef AT_LDK
#undef AT_STK
#undef AT_LDV
#undef AT_STV
}

// ============================================================================
// K3: normalize: sc[row][:] = fp32(eh[row][:]) * linv[row].  780MB streaming.
// ============================================================================
__global__ __launch_bounds__(512) void norm_rows(
    float* __restrict__ sc, const __half* __restrict__ eh,
    const float* __restrict__ linv)
{
    const int r = blockIdx.x;
    const float s = linv[r];
    uint2 u = ((const uint2*)(eh + (size_t)r * Sq))[threadIdx.x];
    __half2 h0 = *(__half2*)&u.x;
    __half2 h1 = *(__half2*)&u.y;
    float2 f0 = __half22float2(h0);
    float2 f1 = __half22float2(h1);
    float4 v;
    v.x = f0.x * s; v.y = f0.y * s;
    v.z = f1.x * s; v.w = f1.y * s;
    ((float4*)(sc + (size_t)r * Sq))[threadIdx.x] = v;
}

// ============================================================================
// K4: final projection out = g_ao(f16) @ Wo^T + bo  (fp16 mma, R11 proven)
// ============================================================================
__global__ __launch_bounds__(256) void outproj_tc(
    const float* __restrict__ W, const float* __restrict__ bias, float* __restrict__ C)
{
    __shared__ __half As[2][128][24];
    __shared__ __half Bs[2][128][24];
    const int tid = threadIdx.x;
    const int lane = tid & 31, wid = tid >> 5;
    const int wm = wid & 1, wn = wid >> 1;
    const int bm = blockIdx.y * 128, bn = blockIdx.x * 128;
    const int lr = lane >> 2, lc = lane & 3;
    const __half* __restrict__ A = g_ao;

    const int row0 = tid >> 1, seg = (tid & 1) * 8;

    const int a_row = lane & 15;
    const int a_cB  = ((lane >> 4) & 1) * 16;
    const int b_row = (lane & 7) + ((lane >> 3) & 1) * 8;
    const int b_cB  = ((lane >> 4) & 1) * 16;

    const uint32_t sA = s2u(&As[0][0][0]);
    const uint32_t sB = s2u(&Bs[0][0][0]);

    uint4 rau;
    float4 rb0, rb1;

#define OP_LD(k0) do { \
    rau = *(const uint4*)(A + (size_t)(bm + row0) * Dm + (k0) + seg); \
    rb0 = *(const float4*)(W + (size_t)(bn + row0) * Dm + (k0) + seg); \
    rb1 = *(const float4*)(W + (size_t)(bn + row0) * Dm + (k0) + seg + 4); \
} while (0)

#define OP_ST(st) do { \
    *(uint4*)&As[st][row0][seg] = rau; \
    *(uint4*)&Bs[st][row0][seg] = f8h(rb0, rb1); \
} while (0)

    float acc[4][4][4];
#pragma unroll
    for (int i = 0; i < 4; i++)
#pragma unroll
        for (int j = 0; j < 4; j++)
#pragma unroll
            for (int t = 0; t < 4; t++) acc[i][j][t] = 0.f;

    OP_LD(0); OP_ST(0); __syncthreads();

    for (int it = 0; it < 64; it++) {
        const int cur = it & 1;
        if (it < 63) OP_LD((it + 1) * 16);

        uint32_t af[4][4], bf[4][2];
#pragma unroll
        for (int mt = 0; mt < 4; mt++)
            ldsm_x4(af[mt][0], af[mt][1], af[mt][2], af[mt][3],
                sA + (cur * 128 + wm * 64 + mt * 16 + a_row) * 48 + a_cB);
#pragma unroll
        for (int ntp = 0; ntp < 2; ntp++) {
            uint32_t r0, r1, r2, r3;
            ldsm_x4(r0, r1, r2, r3,
                sB + (cur * 128 + wn * 32 + ntp * 16 + b_row) * 48 + b_cB);
            bf[2 * ntp][0] = r0; bf[2 * ntp][1] = r2;
            bf[2 * ntp + 1][0] = r1; bf[2 * ntp + 1][1] = r3;
        }
#pragma unroll
        for (int mt = 0; mt < 4; mt++)
#pragma unroll
            for (int nt = 0; nt < 4; nt++)
                mma_f16(acc[mt][nt], af[mt][0], af[mt][1], af[mt][2], af[mt][3],
                        bf[nt][0], bf[nt][1]);

        if (it < 63) OP_ST(cur ^ 1);
        __syncthreads();
    }

#pragma unroll
    for (int mt = 0; mt < 4; mt++) {
#pragma unroll
        for (int nt = 0; nt < 4; nt++) {
            int col = bn + wn * 32 + nt * 8 + lc * 2;
            float b0 = bias[col], b1 = bias[col + 1];
#pragma unroll
            for (int half = 0; half < 2; half++) {
                int m = bm + wm * 64 + mt * 16 + lr + half * 8;
                float2 v;
                v.x = acc[mt][nt][half * 2 + 0] + b0;
                v.y = acc[mt][nt][half * 2 + 1] + b1;
                *(float2*)(C + (size_t)m * Dm + col) = v;
            }
        }
    }
#undef OP_LD
#undef OP_ST
}

// ============================================================================
extern "C" void kernel_launch(void* const* d_in, const int* in_sizes, int n_in,
                              void* d_out, int out_size)
{
    const float* q    = (const float*)d_in[0];
    const float* k    = (const float*)d_in[1];
    const float* v    = (const float*)d_in[2];
    const int*   mask = (const int*)d_in[3];
    const float* Wq   = (const float*)d_in[4];
    const float* bq   = (const float*)d_in[5];
    const float* Wk   = (const float*)d_in[6];
    const float* bk   = (const float*)d_in[7];
    const float* Wv   = (const float*)d_in[8];
    const float* bv   = (const float*)d_in[9];
    const float* Wo   = (const float*)d_in[10];
    const float* bo   = (const float*)d_in[11];

    float* out = (float*)d_out;
    float* sc  = out + (size_t)Bb * Sq * Dm;   // scores_out region

    // attn smem: Qs 36864 + Ks 18432 + Vs 18432 + Ps 36864 = 110592 B
    const int attn_smem = 110592;
    cudaFuncSetAttribute(attn_fused, cudaFuncAttributeMaxDynamicSharedMemorySize, attn_smem);

    dim3 gp(Dm / 128, (Bb * Sq) / 128, 3);
    proj_tc<<<gp, 256>>>(q, k, v, Wq, Wk, Wv, bq, bk, bv);

    dim3 ga(Sq / QT, Bb * Hh);
    attn_fused<<<ga, 512, attn_smem>>>(mask);

    float* linv_ptr;
    __half* eh_ptr;
    cudaGetSymbolAddress((void**)&linv_ptr, g_linv);
    cudaGetSymbolAddress((void**)&eh_ptr,  g_eh);
    norm_rows<<<Bb * Sq * Hh, 512>>>(sc, eh_ptr, linv_ptr);

    dim3 go(Dm / 128, (Bb * Sq) / 128);
    outproj_tc<<<go, 256>>>(Wo, bo, out);
}

// round 14
// speedup vs baseline: 1.5241x; 1.0575x over previous
#include <cuda_runtime.h>
#include <cuda_fp16.h>
#include <cstdint>

#define Bb 2
#define Sq 2048
#define Dm 1024
#define Hh 16
#define Dk 64

// Scratch (allocation-free rule: __device__ globals) — f16 intermediates
__device__ __align__(16) __half g_qh[(size_t)Bb*Hh*Sq*Dk];
__device__ __align__(16) __half g_kh[(size_t)Bb*Hh*Sq*Dk];
__device__ __align__(16) __half g_vh[(size_t)Bb*Hh*Sq*Dk];
__device__ __align__(16) __half g_ao[(size_t)Bb*Sq*Dm];
__device__ __align__(16) float  g_linv[(size_t)Bb*Sq*Hh];
__device__ __align__(16) __half g_eh[(size_t)Bb*Sq*Hh*Sq];      // unnormalized exp(s), fp16
__device__ __align__(16) uint32_t g_mbits[(size_t)Bb*Sq*(Sq/32)]; // packed mask bits

// ---------------------------------------------------------------------------
__device__ __forceinline__ uint32_t h2u(float a, float b) {
    __half2 h = __floats2half2_rn(a, b);
    return *(uint32_t*)&h;
}

__device__ __forceinline__ uint4 f8h(float4 a, float4 b) {
    uint4 r;
    r.x = h2u(a.x, a.y); r.y = h2u(a.z, a.w);
    r.z = h2u(b.x, b.y); r.w = h2u(b.z, b.w);
    return r;
}

__device__ __forceinline__ void mma_f16(float c[4],
    uint32_t a0, uint32_t a1, uint32_t a2, uint32_t a3,
    uint32_t b0, uint32_t b1)
{
    asm volatile(
        "mma.sync.aligned.m16n8k16.row.col.f32.f16.f16.f32 "
        "{%0,%1,%2,%3}, {%4,%5,%6,%7}, {%8,%9}, {%0,%1,%2,%3};"
        : "+f"(c[0]), "+f"(c[1]), "+f"(c[2]), "+f"(c[3])
        : "r"(a0), "r"(a1), "r"(a2), "r"(a3), "r"(b0), "r"(b1));
}

__device__ __forceinline__ void ldsm_x4(uint32_t& r0, uint32_t& r1,
                                        uint32_t& r2, uint32_t& r3, uint32_t addr)
{
    asm volatile("ldmatrix.sync.aligned.m8n8.x4.shared.b16 {%0,%1,%2,%3}, [%4];"
        : "=r"(r0), "=r"(r1), "=r"(r2), "=r"(r3) : "r"(addr));
}

__device__ __forceinline__ void ldsm_x4_t(uint32_t& r0, uint32_t& r1,
                                          uint32_t& r2, uint32_t& r3, uint32_t addr)
{
    asm volatile("ldmatrix.sync.aligned.m8n8.x4.trans.shared.b16 {%0,%1,%2,%3}, [%4];"
        : "=r"(r0), "=r"(r1), "=r"(r2), "=r"(r3) : "r"(addr));
}

__device__ __forceinline__ void cpa16(uint32_t saddr, const void* g) {
    asm volatile("cp.async.cg.shared.global [%0], [%1], 16;" :: "r"(saddr), "l"(g));
}
#define CP_COMMIT() asm volatile("cp.async.commit_group;")
#define CP_WAIT0()  asm volatile("cp.async.wait_group 0;")

__device__ __forceinline__ uint32_t s2u(const void* p) {
    return (uint32_t)__cvta_generic_to_shared(p);
}

// ============================================================================
// K0: pack mask ints -> bits. One thread per output word (32 mask ints).
// ============================================================================
__global__ __launch_bounds__(256) void pack_mask(const int* __restrict__ mask)
{
    size_t wdx = (size_t)blockIdx.x * 256 + threadIdx.x;   // Bb*Sq*64 words
    const int4* p = (const int4*)(mask + wdx * 32);
    uint32_t bits = 0;
#pragma unroll
    for (int i = 0; i < 8; i++) {
        int4 v = p[i];
        bits |= (v.x != 0 ? 1u : 0u) << (i * 4 + 0);
        bits |= (v.y != 0 ? 1u : 0u) << (i * 4 + 1);
        bits |= (v.z != 0 ? 1u : 0u) << (i * 4 + 2);
        bits |= (v.w != 0 ? 1u : 0u) << (i * 4 + 3);
    }
    g_mbits[wdx] = bits;
}

// ============================================================================
// K1: fused Q/K/V projection, fp16 m16n8k16 (R11 proven; fp32 sources keep
// the LDG+cvt+STS path).
// ============================================================================
__global__ __launch_bounds__(256) void proj_tc(
    const float* __restrict__ xq, const float* __restrict__ xk, const float* __restrict__ xv,
    const float* __restrict__ wq, const float* __restrict__ wk, const float* __restrict__ wv,
    const float* __restrict__ bq, const float* __restrict__ bk, const float* __restrict__ bv)
{
    const int which = blockIdx.z;
    const float* __restrict__ A    = which == 0 ? xq : (which == 1 ? xk : xv);
    const float* __restrict__ W    = which == 0 ? wq : (which == 1 ? wk : wv);
    const float* __restrict__ bias = which == 0 ? bq : (which == 1 ? bk : bv);
    __half* __restrict__ dst       = which == 0 ? g_qh : (which == 1 ? g_kh : g_vh);

    __shared__ __half As[2][128][24];
    __shared__ __half Bs[2][128][24];

    const int tid = threadIdx.x;
    const int lane = tid & 31, wid = tid >> 5;
    const int wm = wid & 1, wn = wid >> 1;
    const int bm = blockIdx.y * 128, bn = blockIdx.x * 128;
    const int lr = lane >> 2, lc = lane & 3;

    const int row0 = tid >> 1, seg = (tid & 1) * 8;

    const int a_row = lane & 15;
    const int a_cB  = ((lane >> 4) & 1) * 16;
    const int b_row = (lane & 7) + ((lane >> 3) & 1) * 8;
    const int b_cB  = ((lane >> 4) & 1) * 16;

    const uint32_t sA = s2u(&As[0][0][0]);
    const uint32_t sB = s2u(&Bs[0][0][0]);

    float4 ra0, ra1, rb0, rb1;

#define PJ_LD(k0) do { \
    ra0 = *(const float4*)(A + (size_t)(bm + row0) * Dm + (k0) + seg); \
    ra1 = *(const float4*)(A + (size_t)(bm + row0) * Dm + (k0) + seg + 4); \
    rb0 = *(const float4*)(W + (size_t)(bn + row0) * Dm + (k0) + seg); \
    rb1 = *(const float4*)(W + (size_t)(bn + row0) * Dm + (k0) + seg + 4); \
} while (0)

#define PJ_ST(st) do { \
    *(uint4*)&As[st][row0][seg] = f8h(ra0, ra1); \
    *(uint4*)&Bs[st][row0][seg] = f8h(rb0, rb1); \
} while (0)

    float acc[4][4][4];
#pragma unroll
    for (int i = 0; i < 4; i++)
#pragma unroll
        for (int j = 0; j < 4; j++)
#pragma unroll
            for (int t = 0; t < 4; t++) acc[i][j][t] = 0.f;

    PJ_LD(0); PJ_ST(0); __syncthreads();

    for (int it = 0; it < 64; it++) {
        const int cur = it & 1;
        if (it < 63) PJ_LD((it + 1) * 16);

        uint32_t af[4][4], bf[4][2];
#pragma unroll
        for (int mt = 0; mt < 4; mt++)
            ldsm_x4(af[mt][0], af[mt][1], af[mt][2], af[mt][3],
                sA + (cur * 128 + wm * 64 + mt * 16 + a_row) * 48 + a_cB);
#pragma unroll
        for (int ntp = 0; ntp < 2; ntp++) {
            uint32_t r0, r1, r2, r3;
            ldsm_x4(r0, r1, r2, r3,
                sB + (cur * 128 + wn * 32 + ntp * 16 + b_row) * 48 + b_cB);
            bf[2 * ntp][0] = r0; bf[2 * ntp][1] = r2;
            bf[2 * ntp + 1][0] = r1; bf[2 * ntp + 1][1] = r3;
        }
#pragma unroll
        for (int mt = 0; mt < 4; mt++)
#pragma unroll
            for (int nt = 0; nt < 4; nt++)
                mma_f16(acc[mt][nt], af[mt][0], af[mt][1], af[mt][2], af[mt][3],
                        bf[nt][0], bf[nt][1]);

        if (it < 63) PJ_ST(cur ^ 1);
        __syncthreads();
    }

#pragma unroll
    for (int mt = 0; mt < 4; mt++) {
#pragma unroll
        for (int nt = 0; nt < 4; nt++) {
            int col = bn + wn * 32 + nt * 8 + lc * 2;
            int h = col >> 6, d = col & 63;
            float b0 = bias[col], b1 = bias[col + 1];
#pragma unroll
            for (int half = 0; half < 2; half++) {
                int m = bm + wm * 64 + mt * 16 + lr + half * 8;
                int b = m >> 11;
                int s = m & (Sq - 1);
                __half2 hv = __floats2half2_rn(acc[mt][nt][half * 2 + 0] + b0,
                                               acc[mt][nt][half * 2 + 1] + b1);
                *(__half2*)(dst + (((size_t)(b * Hh + h) * Sq + s) << 6) + d) = hv;
            }
        }
    }
#undef PJ_LD
#undef PJ_ST
}

// ============================================================================
// K2: fused attention (fp16 mma, cp.async staging, hoisted Q frags, bitmask).
// E written fp16 to g_eh; 1/rowsum to g_linv.
// ============================================================================
#define QT 256

__global__ __launch_bounds__(512, 1) void attn_fused()
{
    extern __shared__ char shb[];
    __half (*Qs)[72]     = (__half(*)[72])shb;                  // [q256][d]
    __half (*Ks)[64][72] = (__half(*)[64][72])(shb + 36864);    // [st][tok][d]
    __half (*Vs)[64][72] = (__half(*)[64][72])(shb + 55296);    // [st][tok][d]
    __half (*Ps)[72]     = (__half(*)[72])(shb + 73728);        // [q][k] fp16 staging

    const int bh = blockIdx.y;
    const int b = bh >> 4, h = bh & 15;
    const int q0 = blockIdx.x * QT;
    const __half* qp    = g_qh + ((size_t)bh * Sq + q0) * Dk;
    const __half* kbase = g_kh + (size_t)bh * Sq * Dk;
    const __half* vbase = g_vh + (size_t)bh * Sq * Dk;

    const int tid = threadIdx.x;
    const int lane = tid & 31, w = tid >> 5;          // 16 warps
    const int lr = lane >> 2, lc = lane & 3;
    const int r0 = 16 * w + lr;
    const int qg0 = q0 + r0;

    const int a_row = lane & 15;
    const int a_cB  = ((lane >> 4) & 1) * 16;
    const int b_row = (lane & 7) + ((lane >> 3) & 1) * 8;
    const int b_cB  = ((lane >> 4) & 1) * 16;

    const uint32_t sQ = s2u(&Qs[0][0]);
    const uint32_t sK = s2u(&Ks[0][0][0]);
    const uint32_t sV = s2u(&Vs[0][0][0]);

    const int rA = tid >> 3, segA = (tid & 7) * 8;

#define AT_CPKV(st, kt) do { \
    cpa16(sK + ((st) * 64 + rA) * 144 + segA * 2, kbase + (size_t)((kt) + rA) * Dk + segA); \
    cpa16(sV + ((st) * 64 + rA) * 144 + segA * 2, vbase + (size_t)((kt) + rA) * Dk + segA); \
} while (0)

    // prologue: Q (cp.async) + KV stage 0
#pragma unroll
    for (int t = 0; t < 4; t++) {
        int f = tid + t * 512;
        int row = f >> 3, sg = (f & 7) * 8;
        cpa16(sQ + row * 144 + sg * 2, qp + row * Dk + sg);
    }
    AT_CPKV(0, 0);
    CP_COMMIT();
    CP_WAIT0();
    __syncthreads();

    // hoist Q fragments (loop-invariant per warp)
    uint32_t qfr[4][4];
#pragma unroll
    for (int g = 0; g < 4; g++)
        ldsm_x4(qfr[g][0], qfr[g][1], qfr[g][2], qfr[g][3],
            sQ + (16 * w + a_row) * 144 + g * 32 + a_cB);

    const uint32_t* mb0 = g_mbits + ((size_t)(b * Sq + qg0)) * 64;
    const uint32_t* mb1 = mb0 + 8 * 64;

    float lsum0 = 0.f, lsum1 = 0.f;
    float o_acc[8][4];
#pragma unroll
    for (int nt = 0; nt < 8; nt++)
#pragma unroll
        for (int e = 0; e < 4; e++) o_acc[nt][e] = 0.f;

    for (int it = 0; it < Sq / 64; it++) {
        const int cur = it & 1;
        const int kt = it * 64;
        if (it < Sq / 64 - 1) { AT_CPKV(cur ^ 1, kt + 64); CP_COMMIT(); }

        float acc[8][4];
#pragma unroll
        for (int nt = 0; nt < 8; nt++)
#pragma unroll
            for (int e = 0; e < 4; e++) acc[nt][e] = 0.f;

        // ---- QK^T: 4 k16-groups over d ----
#pragma unroll
        for (int g = 0; g < 4; g++) {
            uint32_t kb[8][2];
#pragma unroll
            for (int ntp = 0; ntp < 4; ntp++) {
                uint32_t r0u, r1u, r2u, r3u;
                ldsm_x4(r0u, r1u, r2u, r3u,
                    sK + (cur * 64 + ntp * 16 + b_row) * 144 + g * 32 + b_cB);
                kb[2 * ntp][0] = r0u; kb[2 * ntp][1] = r2u;
                kb[2 * ntp + 1][0] = r1u; kb[2 * ntp + 1][1] = r3u;
            }
#pragma unroll
            for (int nt = 0; nt < 8; nt++)
                mma_f16(acc[nt], qfr[g][0], qfr[g][1], qfr[g][2], qfr[g][3],
                        kb[nt][0], kb[nt][1]);
        }

        // ---- mask bits, exp, row sums; stage fp16 into Ps ----
        uint2 mw0 = *(const uint2*)(mb0 + (kt >> 5));
        uint2 mw1 = *(const uint2*)(mb1 + (kt >> 5));
#pragma unroll
        for (int nt = 0; nt < 8; nt++) {
            const int p = nt * 8 + lc * 2;
            const uint32_t s0 = ((nt < 4) ? mw0.x : mw0.y) >> (p & 31);
            const uint32_t s1 = ((nt < 4) ? mw1.x : mw1.y) >> (p & 31);
            float e00 = (s0 & 1u) ? __expf(acc[nt][0] * 0.125f) : 0.f;
            float e01 = (s0 & 2u) ? __expf(acc[nt][1] * 0.125f) : 0.f;
            float e10 = (s1 & 1u) ? __expf(acc[nt][2] * 0.125f) : 0.f;
            float e11 = (s1 & 2u) ? __expf(acc[nt][3] * 0.125f) : 0.f;
            lsum0 += e00 + e01;
            lsum1 += e10 + e11;
            acc[nt][0] = e00; acc[nt][1] = e01;
            acc[nt][2] = e10; acc[nt][3] = e11;
            int cl = nt * 8 + lc * 2;
            *(__half2*)&Ps[r0][cl]     = __floats2half2_rn(e00, e01);
            *(__half2*)&Ps[r0 + 8][cl] = __floats2half2_rn(e10, e11);
        }
        __syncthreads();

        // coalesced write of unnormalized E tile (fp16)
#pragma unroll
        for (int t = 0; t < 4; t++) {
            int f = tid + t * 512;
            int row = f >> 3;
            int sg = (f & 7) * 8;
            uint4 v = *(const uint4*)&Ps[row][sg];
            *(uint4*)(g_eh + (((size_t)(b * Sq + q0 + row)) * Hh + h) * Sq + kt + sg) = v;
        }

        // ---- O += E @ V: A from registers, B via ldsm.trans
#pragma unroll
        for (int g = 0; g < 4; g++) {
            uint32_t a0 = h2u(acc[2 * g][0],     acc[2 * g][1]);
            uint32_t a1 = h2u(acc[2 * g][2],     acc[2 * g][3]);
            uint32_t a2 = h2u(acc[2 * g + 1][0], acc[2 * g + 1][1]);
            uint32_t a3 = h2u(acc[2 * g + 1][2], acc[2 * g + 1][3]);
            uint32_t vb[8][2];
#pragma unroll
            for (int ntp = 0; ntp < 4; ntp++) {
                uint32_t r0u, r1u, r2u, r3u;
                ldsm_x4_t(r0u, r1u, r2u, r3u,
                    sV + (cur * 64 + g * 16 + b_row) * 144 + ntp * 32 + b_cB);
                vb[2 * ntp][0] = r0u; vb[2 * ntp][1] = r1u;
                vb[2 * ntp + 1][0] = r2u; vb[2 * ntp + 1][1] = r3u;
            }
#pragma unroll
            for (int nt = 0; nt < 8; nt++)
                mma_f16(o_acc[nt], a0, a1, a2, a3, vb[nt][0], vb[nt][1]);
        }

        if (it < Sq / 64 - 1) CP_WAIT0();
        __syncthreads();
    }

    // reduce row sums over the 4 lc lanes
    lsum0 += __shfl_xor_sync(0xffffffffu, lsum0, 1);
    lsum0 += __shfl_xor_sync(0xffffffffu, lsum0, 2);
    lsum1 += __shfl_xor_sync(0xffffffffu, lsum1, 1);
    lsum1 += __shfl_xor_sync(0xffffffffu, lsum1, 2);
    const float inv0 = 1.0f / lsum0, inv1 = 1.0f / lsum1;

    if (lc == 0) {
        g_linv[((size_t)(b * Sq + qg0)) * Hh + h]     = inv0;
        g_linv[((size_t)(b * Sq + qg0 + 8)) * Hh + h] = inv1;
    }

    // epilogue: write O (scaled, f16) to g_ao
    __half* orow0 = g_ao + (size_t)(b * Sq + qg0) * Dm + h * Dk;
    __half* orow1 = orow0 + 8 * Dm;
#pragma unroll
    for (int nt = 0; nt < 8; nt++) {
        int d = nt * 8 + lc * 2;
        *(__half2*)(orow0 + d) = __floats2half2_rn(o_acc[nt][0] * inv0, o_acc[nt][1] * inv0);
        *(__half2*)(orow1 + d) = __floats2half2_rn(o_acc[nt][2] * inv1, o_acc[nt][3] * inv1);
    }
#undef AT_CPKV
}

// ============================================================================
// K3: normalize: sc[row][:] = fp32(eh[row][:]) * linv[row].
// ============================================================================
__global__ __launch_bounds__(512) void norm_rows(
    float* __restrict__ sc, const __half* __restrict__ eh,
    const float* __restrict__ linv)
{
    const int r = blockIdx.x;
    const float s = linv[r];
    uint2 u = ((const uint2*)(eh + (size_t)r * Sq))[threadIdx.x];
    __half2 h0 = *(__half2*)&u.x;
    __half2 h1 = *(__half2*)&u.y;
    float2 f0 = __half22float2(h0);
    float2 f1 = __half22float2(h1);
    float4 v;
    v.x = f0.x * s; v.y = f0.y * s;
    v.z = f1.x * s; v.w = f1.y * s;
    ((float4*)(sc + (size_t)r * Sq))[threadIdx.x] = v;
}

// ============================================================================
// K4: final projection out = g_ao(f16) @ Wo^T + bo  (A via cp.async)
// ============================================================================
__global__ __launch_bounds__(256) void outproj_tc(
    const float* __restrict__ W, const float* __restrict__ bias, float* __restrict__ C)
{
    __shared__ __half As[2][128][24];
    __shared__ __half Bs[2][128][24];
    const int tid = threadIdx.x;
    const int lane = tid & 31, wid = tid >> 5;
    const int wm = wid & 1, wn = wid >> 1;
    const int bm = blockIdx.y * 128, bn = blockIdx.x * 128;
    const int lr = lane >> 2, lc = lane & 3;
    const __half* __restrict__ A = g_ao;

    const int row0 = tid >> 1, seg = (tid & 1) * 8;

    const int a_row = lane & 15;
    const int a_cB  = ((lane >> 4) & 1) * 16;
    const int b_row = (lane & 7) + ((lane >> 3) & 1) * 8;
    const int b_cB  = ((lane >> 4) & 1) * 16;

    const uint32_t sA = s2u(&As[0][0][0]);
    const uint32_t sB = s2u(&Bs[0][0][0]);

    float4 rb0, rb1;

#define OP_CPA(st, k0) \
    cpa16(sA + ((st) * 128 + row0) * 48 + seg * 2, A + (size_t)(bm + row0) * Dm + (k0) + seg)

#define OP_LDB(k0) do { \
    rb0 = *(const float4*)(W + (size_t)(bn + row0) * Dm + (k0) + seg); \
    rb1 = *(const float4*)(W + (size_t)(bn + row0) * Dm + (k0) + seg + 4); \
} while (0)

#define OP_STB(st) do { \
    *(uint4*)&Bs[st][row0][seg] = f8h(rb0, rb1); \
} while (0)

    float acc[4][4][4];
#pragma unroll
    for (int i = 0; i < 4; i++)
#pragma unroll
        for (int j = 0; j < 4; j++)
#pragma unroll
            for (int t = 0; t < 4; t++) acc[i][j][t] = 0.f;

    OP_CPA(0, 0); CP_COMMIT(); OP_LDB(0); OP_STB(0); CP_WAIT0(); __syncthreads();

    for (int it = 0; it < 64; it++) {
        const int cur = it & 1;
        if (it < 63) { OP_CPA(cur ^ 1, (it + 1) * 16); CP_COMMIT(); OP_LDB((it + 1) * 16); }

        uint32_t af[4][4], bf[4][2];
#pragma unroll
        for (int mt = 0; mt < 4; mt++)
            ldsm_x4(af[mt][0], af[mt][1], af[mt][2], af[mt][3],
                sA + (cur * 128 + wm * 64 + mt * 16 + a_row) * 48 + a_cB);
#pragma unroll
        for (int ntp = 0; ntp < 2; ntp++) {
            uint32_t r0, r1, r2, r3;
            ldsm_x4(r0, r1, r2, r3,
                sB + (cur * 128 + wn * 32 + ntp * 16 + b_row) * 48 + b_cB);
            bf[2 * ntp][0] = r0; bf[2 * ntp][1] = r2;
            bf[2 * ntp + 1][0] = r1; bf[2 * ntp + 1][1] = r3;
        }
#pragma unroll
        for (int mt = 0; mt < 4; mt++)
#pragma unroll
            for (int nt = 0; nt < 4; nt++)
                mma_f16(acc[mt][nt], af[mt][0], af[mt][1], af[mt][2], af[mt][3],
                        bf[nt][0], bf[nt][1]);

        if (it < 63) { OP_STB(cur ^ 1); CP_WAIT0(); }
        __syncthreads();
    }

#pragma unroll
    for (int mt = 0; mt < 4; mt++) {
#pragma unroll
        for (int nt = 0; nt < 4; nt++) {
            int col = bn + wn * 32 + nt * 8 + lc * 2;
            float b0 = bias[col], b1 = bias[col + 1];
#pragma unroll
            for (int half = 0; half < 2; half++) {
                int m = bm + wm * 64 + mt * 16 + lr + half * 8;
                float2 v;
                v.x = acc[mt][nt][half * 2 + 0] + b0;
                v.y = acc[mt][nt][half * 2 + 1] + b1;
                *(float2*)(C + (size_t)m * Dm + col) = v;
            }
        }
    }
#undef OP_CPA
#undef OP_LDB
#undef OP_STB
}

// ============================================================================
extern "C" void kernel_launch(void* const* d_in, const int* in_sizes, int n_in,
                              void* d_out, int out_size)
{
    const float* q    = (const float*)d_in[0];
    const float* k    = (const float*)d_in[1];
    const float* v    = (const float*)d_in[2];
    const int*   mask = (const int*)d_in[3];
    const float* Wq   = (const float*)d_in[4];
    const float* bq   = (const float*)d_in[5];
    const float* Wk   = (const float*)d_in[6];
    const float* bk   = (const float*)d_in[7];
    const float* Wv   = (const float*)d_in[8];
    const float* bv   = (const float*)d_in[9];
    const float* Wo   = (const float*)d_in[10];
    const float* bo   = (const float*)d_in[11];

    float* out = (float*)d_out;
    float* sc  = out + (size_t)Bb * Sq * Dm;   // scores_out region

    const int attn_smem = 110592;
    cudaFuncSetAttribute(attn_fused, cudaFuncAttributeMaxDynamicSharedMemorySize, attn_smem);

    pack_mask<<<(Bb * Sq * (Sq / 32)) / 256, 256>>>(mask);

    dim3 gp(Dm / 128, (Bb * Sq) / 128, 3);
    proj_tc<<<gp, 256>>>(q, k, v, Wq, Wk, Wv, bq, bk, bv);

    dim3 ga(Sq / QT, Bb * Hh);
    attn_fused<<<ga, 512, attn_smem>>>();

    float* linv_ptr;
    __half* eh_ptr;
    cudaGetSymbolAddress((void**)&linv_ptr, g_linv);
    cudaGetSymbolAddress((void**)&eh_ptr,  g_eh);
    norm_rows<<<Bb * Sq * Hh, 512>>>(sc, eh_ptr, linv_ptr);

    dim3 go(Dm / 128, (Bb * Sq) / 128);
    outproj_tc<<<go, 256>>>(Wo, bo, out);
}